// round 1
// baseline (speedup 1.0000x reference)
#include <cuda_runtime.h>
#include <math.h>

#define BATCH  2
#define CDIM   512
#define NTOK   4096
#define HEADS  8
#define HD     64
#define GROUPS 32

// ---------------- scratch (static device globals; no allocations) ----------
__device__ float g_h [(size_t)BATCH*CDIM*NTOK];   // normalized x, layout [B][C][N]
__device__ float g_q [(size_t)BATCH*NTOK*CDIM];   // Q, layout [B][N][C]
__device__ float g_kt[(size_t)BATCH*CDIM*NTOK];   // K, layout [B][C][N]  (pre-transposed)
__device__ float g_v [(size_t)BATCH*NTOK*CDIM];   // V, layout [B][N][C]
__device__ float g_o [(size_t)BATCH*CDIM*NTOK];   // attn out, layout [B][C][N]
__device__ float g_wt[4*(size_t)CDIM*CDIM];       // Wq^T, Wk^T, Wv^T, Wo^T : [k][m]

// ---------------- weight transpose: Wt[k][m] = W[m][k] ---------------------
__global__ void k_transpose(const float* __restrict__ W0, const float* __restrict__ W1,
                            const float* __restrict__ W2, const float* __restrict__ W3)
{
    const float* srcs[4] = {W0, W1, W2, W3};
    const float* W = srcs[blockIdx.z];
    float* dst = g_wt + (size_t)blockIdx.z * CDIM * CDIM;

    __shared__ float tile[32][33];
    int x = blockIdx.x * 32 + threadIdx.x;
    int y = blockIdx.y * 32 + threadIdx.y;
#pragma unroll
    for (int i = 0; i < 32; i += 8)
        tile[threadIdx.y + i][threadIdx.x] = W[(size_t)(y + i) * CDIM + x];
    __syncthreads();
    int x2 = blockIdx.y * 32 + threadIdx.x;
    int y2 = blockIdx.x * 32 + threadIdx.y;
#pragma unroll
    for (int i = 0; i < 32; i += 8)
        dst[(size_t)(y2 + i) * CDIM + x2] = tile[threadIdx.x][threadIdx.y + i];
}

// ---------------- GroupNorm: one block per (b, g); region is contiguous ----
__global__ void k_groupnorm(const float* __restrict__ x,
                            const float* __restrict__ gamma,
                            const float* __restrict__ beta)
{
    int b = blockIdx.x >> 5;
    int g = blockIdx.x & 31;
    size_t base = ((size_t)b * CDIM + g * 16) * NTOK;     // 65536 contiguous floats
    const float4* xp = (const float4*)(x + base);
    float4* hp = (float4*)(g_h + base);

    float s = 0.f, ss = 0.f;
    for (int i = threadIdx.x; i < 16384; i += 256) {
        float4 v = xp[i];
        s  += v.x + v.y + v.z + v.w;
        ss += v.x*v.x + v.y*v.y + v.z*v.z + v.w*v.w;
    }
#pragma unroll
    for (int off = 16; off > 0; off >>= 1) {
        s  += __shfl_xor_sync(0xffffffffu, s,  off);
        ss += __shfl_xor_sync(0xffffffffu, ss, off);
    }
    __shared__ float red[18];
    int warp = threadIdx.x >> 5;
    if ((threadIdx.x & 31) == 0) { red[warp] = s; red[8 + warp] = ss; }
    __syncthreads();
    if (threadIdx.x == 0) {
        float S = 0.f, SS = 0.f;
        for (int w = 0; w < 8; w++) { S += red[w]; SS += red[8 + w]; }
        float mean = S * (1.0f / 65536.0f);
        float var  = SS * (1.0f / 65536.0f) - mean * mean;
        red[16] = mean;
        red[17] = rsqrtf(var + 1e-5f);
    }
    __syncthreads();
    float mean = red[16], rstd = red[17];

    for (int i = threadIdx.x; i < 16384; i += 256) {
        int c = g * 16 + (i >> 10);          // element channel (4096 floats / channel)
        float ga = gamma[c] * rstd;
        float be = beta[c] - mean * ga;
        float4 v = xp[i];
        v.x = v.x * ga + be; v.y = v.y * ga + be;
        v.z = v.z * ga + be; v.w = v.w * ga + be;
        hp[i] = v;
    }
}

// ---------------- GEMM: Y[n][m] = sum_k A[k][n] * Wt[k][m] + bias[m] -------
// src_sel: 0 -> g_h, 1 -> g_o.  dst_sel: 0 g_q (row), 1 g_kt (transposed),
// 2 g_v (row), 3 out (transposed + residual).
__global__ void __launch_bounds__(256) k_gemm(int src_sel, int wt_idx,
                                              const float* __restrict__ bias,
                                              const float* __restrict__ resid,
                                              float* __restrict__ outp,
                                              int dst_sel)
{
    int b  = blockIdx.z;
    int n0 = blockIdx.x * 64;
    int m0 = blockIdx.y * 64;

    const float* A  = (src_sel == 0 ? g_h : g_o) + (size_t)b * CDIM * NTOK;
    const float* Wt = g_wt + (size_t)wt_idx * CDIM * CDIM;

    __shared__ float As[16][64];
    __shared__ float Bs[16][64];
    __shared__ float Cs[64 * 65];

    int tid = threadIdx.x;
    int tx = tid & 15, ty = tid >> 4;
    int lkk = tid >> 4, lnn = (tid & 15) << 2;

    float acc[4][4];
#pragma unroll
    for (int i = 0; i < 4; i++)
#pragma unroll
        for (int j = 0; j < 4; j++) acc[i][j] = 0.f;

    for (int k0 = 0; k0 < CDIM; k0 += 16) {
        *(float4*)&As[lkk][lnn] = *(const float4*)&A [(size_t)(k0 + lkk) * NTOK + n0 + lnn];
        *(float4*)&Bs[lkk][lnn] = *(const float4*)&Wt[(size_t)(k0 + lkk) * CDIM + m0 + lnn];
        __syncthreads();
#pragma unroll
        for (int kk = 0; kk < 16; kk++) {
            float4 a4 = *(const float4*)&As[kk][ty << 2];
            float4 b4 = *(const float4*)&Bs[kk][tx << 2];
            float av[4] = {a4.x, a4.y, a4.z, a4.w};
            float bv[4] = {b4.x, b4.y, b4.z, b4.w};
#pragma unroll
            for (int i = 0; i < 4; i++)
#pragma unroll
                for (int j = 0; j < 4; j++) acc[i][j] += av[i] * bv[j];
        }
        __syncthreads();
    }

    float4 bi4 = *(const float4*)&bias[m0 + (tx << 2)];
    float bv[4] = {bi4.x, bi4.y, bi4.z, bi4.w};
#pragma unroll
    for (int i = 0; i < 4; i++)
#pragma unroll
        for (int j = 0; j < 4; j++) acc[i][j] += bv[j];

    if (dst_sel == 0 || dst_sel == 2) {
        float* Y = (dst_sel == 0 ? g_q : g_v);
#pragma unroll
        for (int i = 0; i < 4; i++) {
            size_t row = (size_t)b * NTOK + n0 + (ty << 2) + i;
            *(float4*)&Y[row * CDIM + m0 + (tx << 2)] =
                make_float4(acc[i][0], acc[i][1], acc[i][2], acc[i][3]);
        }
    } else {
        // transposed store: Y[b][m][n]
#pragma unroll
        for (int i = 0; i < 4; i++)
#pragma unroll
            for (int j = 0; j < 4; j++)
                Cs[((ty << 2) + i) * 65 + (tx << 2) + j] = acc[i][j];
        __syncthreads();
        float* Y = (dst_sel == 1 ? g_kt : outp);
        for (int e = tid; e < 4096; e += 256) {
            int mL = e >> 6, nL = e & 63;
            float v = Cs[nL * 65 + mL];
            size_t idx = ((size_t)b * CDIM + m0 + mL) * NTOK + n0 + nL;
            if (dst_sel == 3) v += resid[idx];
            Y[idx] = v;
        }
    }
}

// ---------------- attention: flash-style, 64 q-rows per block --------------
__global__ void __launch_bounds__(256) k_attn()
{
    int n0 = blockIdx.x * 64;
    int h  = blockIdx.y;
    int b  = blockIdx.z;

    __shared__ float sm[12288];          // exactly 48 KB
    float* Qs  = sm;                     // [64][64] plain
    float* Kts = sm + 4096;              // [64(d)][64(j)] XOR-swizzled; reused as Ps[64][64]
    float* Vs  = sm + 8192;              // [64(j)][64(c)] plain

    int tid = threadIdx.x;
    int tx = tid & 15, ty = tid >> 4;

    // load + pre-scale Q tile: fold (1/sqrt(64)) * log2(e) into Q
    const float SCL = 0.125f * 1.4426950408889634f;
    {
        int c4 = (tid & 15) << 2;
        int r  = tid >> 4;
#pragma unroll
        for (int it = 0; it < 4; it++) {
            int rr = r + it * 16;
            float4 v = *(const float4*)&g_q[((size_t)b * NTOK + n0 + rr) * CDIM + h * HD + c4];
            v.x *= SCL; v.y *= SCL; v.z *= SCL; v.w *= SCL;
            *(float4*)&Qs[rr * 64 + c4] = v;
        }
    }

    float m_i[4], l_i[4], oa[4][4];
#pragma unroll
    for (int i = 0; i < 4; i++) {
        m_i[i] = -1e30f; l_i[i] = 0.f;
#pragma unroll
        for (int j = 0; j < 4; j++) oa[i][j] = 0.f;
    }

    const float* KtB = g_kt + ((size_t)b * CDIM + h * HD) * NTOK;

    for (int j0 = 0; j0 < NTOK; j0 += 64) {
        // load K tile (swizzled transpose source is already [d][n]) and V tile
        {
            int c4 = tid & 15;
            int dd = tid >> 4;
#pragma unroll
            for (int it = 0; it < 4; it++) {
                int d = dd + it * 16;
                float4 kv = *(const float4*)&KtB[(size_t)d * NTOK + j0 + (c4 << 2)];
                *(float4*)&Kts[d * 64 + ((c4 ^ (d & 7)) << 2)] = kv;
                float4 vv = *(const float4*)&g_v[((size_t)b * NTOK + j0 + d) * CDIM + h * HD + (c4 << 2)];
                *(float4*)&Vs[d * 64 + (c4 << 2)] = vv;
            }
        }
        __syncthreads();

        // S = Q * K^T   (S already in log2 space because Q was pre-scaled)
        float s[4][4];
#pragma unroll
        for (int i = 0; i < 4; i++)
#pragma unroll
            for (int j = 0; j < 4; j++) s[i][j] = 0.f;

#pragma unroll 16
        for (int d = 0; d < 64; d++) {
            float4 k4 = *(const float4*)&Kts[d * 64 + ((tx ^ (d & 7)) << 2)];
            float kv[4] = {k4.x, k4.y, k4.z, k4.w};
#pragma unroll
            for (int i = 0; i < 4; i++) {
                float qv = Qs[((ty << 2) + i) * 64 + d];
#pragma unroll
                for (int j = 0; j < 4; j++) s[i][j] += qv * kv[j];
            }
        }

        // online softmax (base-2), rows reduced across the 16 tx lanes
        float mnew[4], alpha[4], rs[4];
#pragma unroll
        for (int i = 0; i < 4; i++) {
            float mt = fmaxf(fmaxf(s[i][0], s[i][1]), fmaxf(s[i][2], s[i][3]));
#pragma unroll
            for (int off = 1; off < 16; off <<= 1)
                mt = fmaxf(mt, __shfl_xor_sync(0xffffffffu, mt, off));
            mnew[i]  = fmaxf(m_i[i], mt);
            alpha[i] = exp2f(m_i[i] - mnew[i]);
            float r = 0.f;
#pragma unroll
            for (int j = 0; j < 4; j++) {
                s[i][j] = exp2f(s[i][j] - mnew[i]);
                r += s[i][j];
            }
#pragma unroll
            for (int off = 1; off < 16; off <<= 1)
                r += __shfl_xor_sync(0xffffffffu, r, off);
            rs[i] = r;
        }
#pragma unroll
        for (int i = 0; i < 4; i++) {
            l_i[i] = l_i[i] * alpha[i] + rs[i];
            m_i[i] = mnew[i];
#pragma unroll
            for (int j = 0; j < 4; j++) oa[i][j] *= alpha[i];
        }

        __syncthreads();   // everyone done reading Kts
        // store P into the (dead) K buffer, plain stride-64
#pragma unroll
        for (int i = 0; i < 4; i++)
            *(float4*)&Kts[((ty << 2) + i) * 64 + (tx << 2)] =
                make_float4(s[i][0], s[i][1], s[i][2], s[i][3]);
        __syncthreads();

        // O += P * V
#pragma unroll 8
        for (int j = 0; j < 64; j++) {
            float4 v4 = *(const float4*)&Vs[j * 64 + (tx << 2)];
            float vv[4] = {v4.x, v4.y, v4.z, v4.w};
#pragma unroll
            for (int i = 0; i < 4; i++) {
                float pv = Kts[((ty << 2) + i) * 64 + j];
#pragma unroll
                for (int c = 0; c < 4; c++) oa[i][c] += pv * vv[c];
            }
        }
        __syncthreads();   // before next tile overwrites Kts / Vs
    }

    // epilogue: normalize, stage, write g_o transposed [B][C][N]
    float* Cs = sm + 4096;               // 64*65 floats; Kts+Vs are dead
#pragma unroll
    for (int i = 0; i < 4; i++) {
        float inv = 1.0f / l_i[i];
#pragma unroll
        for (int j = 0; j < 4; j++)
            Cs[((ty << 2) + i) * 65 + (tx << 2) + j] = oa[i][j] * inv;
    }
    __syncthreads();
    for (int e = tid; e < 4096; e += 256) {
        int cL = e >> 6, nL = e & 63;
        g_o[((size_t)b * CDIM + h * HD + cL) * NTOK + n0 + nL] = Cs[nL * 65 + cL];
    }
}

// ---------------- launch ----------------------------------------------------
extern "C" void kernel_launch(void* const* d_in, const int* in_sizes, int n_in,
                              void* d_out, int out_size)
{
    const float* x     = (const float*)d_in[0];
    const float* gamma = (const float*)d_in[1];
    const float* beta  = (const float*)d_in[2];
    const float* Wq    = (const float*)d_in[3];
    const float* bq    = (const float*)d_in[4];
    const float* Wk    = (const float*)d_in[5];
    const float* bk    = (const float*)d_in[6];
    const float* Wv    = (const float*)d_in[7];
    const float* bv    = (const float*)d_in[8];
    const float* Wo    = (const float*)d_in[9];
    const float* bo    = (const float*)d_in[10];
    float* out = (float*)d_out;

    k_transpose<<<dim3(CDIM/32, CDIM/32, 4), dim3(32, 8)>>>(Wq, Wk, Wv, Wo);
    k_groupnorm<<<BATCH * GROUPS, 256>>>(x, gamma, beta);

    dim3 gg(NTOK / 64, CDIM / 64, BATCH);
    k_gemm<<<gg, 256>>>(0, 0, bq, nullptr, nullptr, 0);  // Q  -> g_q  [B][N][C]
    k_gemm<<<gg, 256>>>(0, 1, bk, nullptr, nullptr, 1);  // K  -> g_kt [B][C][N]
    k_gemm<<<gg, 256>>>(0, 2, bv, nullptr, nullptr, 2);  // V  -> g_v  [B][N][C]

    k_attn<<<dim3(NTOK / 64, HEADS, BATCH), 256>>>();

    k_gemm<<<gg, 256>>>(1, 3, bo, x, out, 3);            // out = x + o @ Wo^T + bo
}

// round 2
// speedup vs baseline: 1.7080x; 1.7080x over previous
#include <cuda_runtime.h>
#include <math.h>

#define BATCH  2
#define CDIM   512
#define NTOK   4096
#define HEADS  8
#define HD     64
#define GROUPS 32

// ---------------- scratch (static device globals; no allocations) ----------
__device__ float g_h [(size_t)BATCH*CDIM*NTOK];   // normalized x, layout [B][C][N]
__device__ float g_q [(size_t)BATCH*NTOK*CDIM];   // Q, layout [B][N][C]
__device__ float g_k [(size_t)BATCH*NTOK*CDIM];   // K, layout [B][N][C]
__device__ float g_vt[(size_t)BATCH*CDIM*NTOK];   // V, layout [B][C][N] (transposed)
__device__ float g_o [(size_t)BATCH*CDIM*NTOK];   // attn out, layout [B][C][N]
__device__ float g_wt[4*(size_t)CDIM*CDIM];       // Wq^T, Wk^T, Wv^T, Wo^T : [k][m]

// ---------------- helpers ---------------------------------------------------
__device__ __forceinline__ float tf32r(float x) {
    asm("cvt.rna.tf32.f32 %0, %0;" : "+f"(x));
    return x;
}

__device__ __forceinline__ void mma_tf32(float& d0, float& d1, float& d2, float& d3,
                                         float a0, float a1, float a2, float a3,
                                         float b0, float b1)
{
    asm volatile("mma.sync.aligned.m16n8k8.row.col.f32.tf32.tf32.f32 "
                 "{%0,%1,%2,%3},{%4,%5,%6,%7},{%8,%9},{%0,%1,%2,%3};"
                 : "+f"(d0), "+f"(d1), "+f"(d2), "+f"(d3)
                 : "f"(a0), "f"(a1), "f"(a2), "f"(a3), "f"(b0), "f"(b1));
}

// ---------------- weight transpose: Wt[k][m] = W[m][k] ---------------------
__global__ void k_transpose(const float* __restrict__ W0, const float* __restrict__ W1,
                            const float* __restrict__ W2, const float* __restrict__ W3)
{
    const float* srcs[4] = {W0, W1, W2, W3};
    const float* W = srcs[blockIdx.z];
    float* dst = g_wt + (size_t)blockIdx.z * CDIM * CDIM;

    __shared__ float tile[32][33];
    int x = blockIdx.x * 32 + threadIdx.x;
    int y = blockIdx.y * 32 + threadIdx.y;
#pragma unroll
    for (int i = 0; i < 32; i += 8)
        tile[threadIdx.y + i][threadIdx.x] = W[(size_t)(y + i) * CDIM + x];
    __syncthreads();
    int x2 = blockIdx.y * 32 + threadIdx.x;
    int y2 = blockIdx.x * 32 + threadIdx.y;
#pragma unroll
    for (int i = 0; i < 32; i += 8)
        dst[(size_t)(y2 + i) * CDIM + x2] = tile[threadIdx.x][threadIdx.y + i];
}

// ---------------- GroupNorm: one block per (b, g); region is contiguous ----
__global__ void k_groupnorm(const float* __restrict__ x,
                            const float* __restrict__ gamma,
                            const float* __restrict__ beta)
{
    int b = blockIdx.x >> 5;
    int g = blockIdx.x & 31;
    size_t base = ((size_t)b * CDIM + g * 16) * NTOK;     // 65536 contiguous floats
    const float4* xp = (const float4*)(x + base);
    float4* hp = (float4*)(g_h + base);

    float s = 0.f, ss = 0.f;
    for (int i = threadIdx.x; i < 16384; i += 256) {
        float4 v = xp[i];
        s  += v.x + v.y + v.z + v.w;
        ss += v.x*v.x + v.y*v.y + v.z*v.z + v.w*v.w;
    }
#pragma unroll
    for (int off = 16; off > 0; off >>= 1) {
        s  += __shfl_xor_sync(0xffffffffu, s,  off);
        ss += __shfl_xor_sync(0xffffffffu, ss, off);
    }
    __shared__ float red[18];
    int warp = threadIdx.x >> 5;
    if ((threadIdx.x & 31) == 0) { red[warp] = s; red[8 + warp] = ss; }
    __syncthreads();
    if (threadIdx.x == 0) {
        float S = 0.f, SS = 0.f;
        for (int w = 0; w < 8; w++) { S += red[w]; SS += red[8 + w]; }
        float mean = S * (1.0f / 65536.0f);
        float var  = SS * (1.0f / 65536.0f) - mean * mean;
        red[16] = mean;
        red[17] = rsqrtf(var + 1e-5f);
    }
    __syncthreads();
    float mean = red[16], rstd = red[17];

    for (int i = threadIdx.x; i < 16384; i += 256) {
        int c = g * 16 + (i >> 10);          // element channel (4096 floats / channel)
        float ga = gamma[c] * rstd;
        float be = beta[c] - mean * ga;
        float4 v = xp[i];
        v.x = v.x * ga + be; v.y = v.y * ga + be;
        v.z = v.z * ga + be; v.w = v.w * ga + be;
        hp[i] = v;
    }
}

// ---------------- GEMM: Y[n][m] = sum_k A[k][n] * Wt[k][m] + bias[m] -------
// dst_sel: 0 -> g_q row-major, 1 -> g_k row-major,
//          2 -> g_vt transposed, 3 -> outp transposed + residual
__global__ void __launch_bounds__(256) k_gemm(int src_sel, int wt_idx,
                                              const float* __restrict__ bias,
                                              const float* __restrict__ resid,
                                              float* __restrict__ outp,
                                              int dst_sel)
{
    int b  = blockIdx.z;
    int n0 = blockIdx.x * 64;
    int m0 = blockIdx.y * 64;

    const float* A  = (src_sel == 0 ? g_h : g_o) + (size_t)b * CDIM * NTOK;
    const float* Wt = g_wt + (size_t)wt_idx * CDIM * CDIM;

    __shared__ float As[16][64];
    __shared__ float Bs[16][64];
    __shared__ float Cs[64 * 65];

    int tid = threadIdx.x;
    int tx = tid & 15, ty = tid >> 4;
    int lkk = tid >> 4, lnn = (tid & 15) << 2;

    float acc[4][4];
#pragma unroll
    for (int i = 0; i < 4; i++)
#pragma unroll
        for (int j = 0; j < 4; j++) acc[i][j] = 0.f;

    for (int k0 = 0; k0 < CDIM; k0 += 16) {
        *(float4*)&As[lkk][lnn] = *(const float4*)&A [(size_t)(k0 + lkk) * NTOK + n0 + lnn];
        *(float4*)&Bs[lkk][lnn] = *(const float4*)&Wt[(size_t)(k0 + lkk) * CDIM + m0 + lnn];
        __syncthreads();
#pragma unroll
        for (int kk = 0; kk < 16; kk++) {
            float4 a4 = *(const float4*)&As[kk][ty << 2];
            float4 b4 = *(const float4*)&Bs[kk][tx << 2];
            float av[4] = {a4.x, a4.y, a4.z, a4.w};
            float bv[4] = {b4.x, b4.y, b4.z, b4.w};
#pragma unroll
            for (int i = 0; i < 4; i++)
#pragma unroll
                for (int j = 0; j < 4; j++) acc[i][j] += av[i] * bv[j];
        }
        __syncthreads();
    }

    float4 bi4 = *(const float4*)&bias[m0 + (tx << 2)];
    float bv[4] = {bi4.x, bi4.y, bi4.z, bi4.w};
#pragma unroll
    for (int i = 0; i < 4; i++)
#pragma unroll
        for (int j = 0; j < 4; j++) acc[i][j] += bv[j];

    if (dst_sel <= 1) {
        float* Y = (dst_sel == 0 ? g_q : g_k);
#pragma unroll
        for (int i = 0; i < 4; i++) {
            size_t row = (size_t)b * NTOK + n0 + (ty << 2) + i;
            *(float4*)&Y[row * CDIM + m0 + (tx << 2)] =
                make_float4(acc[i][0], acc[i][1], acc[i][2], acc[i][3]);
        }
    } else {
        // transposed store: Y[b][m][n]
#pragma unroll
        for (int i = 0; i < 4; i++)
#pragma unroll
            for (int j = 0; j < 4; j++)
                Cs[((ty << 2) + i) * 65 + (tx << 2) + j] = acc[i][j];
        __syncthreads();
        float* Y = (dst_sel == 2 ? g_vt : outp);
        for (int e = tid; e < 4096; e += 256) {
            int mL = e >> 6, nL = e & 63;
            float v = Cs[nL * 65 + mL];
            size_t idx = ((size_t)b * CDIM + m0 + mL) * NTOK + n0 + nL;
            if (dst_sel == 3) v += resid[idx];
            Y[idx] = v;
        }
    }
}

// ---------------- attention: flash-style, tf32 mma.sync --------------------
// Block: 128 query rows, 8 warps (warp w owns rows w*16..w*16+15).
// Per j-iter: 64 keys. K tile Ks[j][d], V tile Vs[c][j], both stride 69
// (conflict-free for float4 staging, all fragment loads, and epilogue reads).
#define STR 69

__global__ void __launch_bounds__(256) k_attn()
{
    __shared__ float sm[128 * STR];      // 35328 B union: Qs / (Ks+Vs) / Os
    float* Ks = sm;                      // [64][STR]
    float* Vs = sm + 64 * STR;           // [64][STR]

    int tid  = threadIdx.x;
    int lane = tid & 31, warp = tid >> 5;
    int r = lane >> 2, q = lane & 3;     // quad row / quad col
    int n0 = blockIdx.x * 128;
    int h  = blockIdx.y;
    int b  = blockIdx.z;

    const float SCL = 0.125f * 1.4426950408889634f;  // (1/sqrt(64)) * log2(e)

    // ---- stage Q (pre-scaled, tf32-rounded), then lift to register frags ----
    {
        const float* Qg = g_q + ((size_t)b * NTOK + n0) * CDIM + h * HD;
        int row = tid >> 4, c4 = (tid & 15) << 2;
#pragma unroll
        for (int it = 0; it < 8; it++) {
            int rr = row + it * 16;
            float4 v = *(const float4*)&Qg[(size_t)rr * CDIM + c4];
            sm[rr * STR + c4 + 0] = tf32r(v.x * SCL);
            sm[rr * STR + c4 + 1] = tf32r(v.y * SCL);
            sm[rr * STR + c4 + 2] = tf32r(v.z * SCL);
            sm[rr * STR + c4 + 3] = tf32r(v.w * SCL);
        }
    }
    __syncthreads();

    float aq[8][4];
    {
        int rb = warp * 16 + r;
#pragma unroll
        for (int kt = 0; kt < 8; kt++) {
            int c = kt * 8 + q;
            aq[kt][0] = sm[rb * STR + c];
            aq[kt][1] = sm[(rb + 8) * STR + c];
            aq[kt][2] = sm[rb * STR + c + 4];
            aq[kt][3] = sm[(rb + 8) * STR + c + 4];
        }
    }
    __syncthreads();

    float o[8][4];
#pragma unroll
    for (int i = 0; i < 8; i++)
#pragma unroll
        for (int j = 0; j < 4; j++) o[i][j] = 0.f;
    float m0 = -1e30f, m1 = -1e30f, l0 = 0.f, l1 = 0.f;

    const float* Kg = g_k  + (size_t)b * NTOK * CDIM + h * HD;
    const float* Vg = g_vt + ((size_t)b * CDIM + h * HD) * NTOK;

    int src1 = (lane & ~3) | (q >> 1);
    int src2 = src1 + 2;
    bool par = (q & 1) != 0;

    for (int j0 = 0; j0 < NTOK; j0 += 64) {
        // ---- stage K and V tiles (tf32-rounded) ----
        {
            int row = tid >> 4, c4 = (tid & 15) << 2;
#pragma unroll
            for (int it = 0; it < 4; it++) {
                int rr = row + it * 16;
                float4 kv = *(const float4*)&Kg[(size_t)(j0 + rr) * CDIM + c4];
                Ks[rr * STR + c4 + 0] = tf32r(kv.x);
                Ks[rr * STR + c4 + 1] = tf32r(kv.y);
                Ks[rr * STR + c4 + 2] = tf32r(kv.z);
                Ks[rr * STR + c4 + 3] = tf32r(kv.w);
                float4 vv = *(const float4*)&Vg[(size_t)rr * NTOK + j0 + c4];
                Vs[rr * STR + c4 + 0] = tf32r(vv.x);
                Vs[rr * STR + c4 + 1] = tf32r(vv.y);
                Vs[rr * STR + c4 + 2] = tf32r(vv.z);
                Vs[rr * STR + c4 + 3] = tf32r(vv.w);
            }
        }
        __syncthreads();

        // ---- S = Q * K^T (already in log2 space; Q pre-scaled) ----
        float s[8][4];
#pragma unroll
        for (int i = 0; i < 8; i++)
#pragma unroll
            for (int j = 0; j < 4; j++) s[i][j] = 0.f;

#pragma unroll
        for (int kt = 0; kt < 8; kt++) {
#pragma unroll
            for (int nt = 0; nt < 8; nt++) {
                float b0 = Ks[(nt * 8 + r) * STR + kt * 8 + q];
                float b1 = Ks[(nt * 8 + r) * STR + kt * 8 + q + 4];
                mma_tf32(s[nt][0], s[nt][1], s[nt][2], s[nt][3],
                         aq[kt][0], aq[kt][1], aq[kt][2], aq[kt][3], b0, b1);
            }
        }

        // ---- online softmax (base-2); rows live in quads ----
        float mx0 = -1e30f, mx1 = -1e30f;
#pragma unroll
        for (int nt = 0; nt < 8; nt++) {
            mx0 = fmaxf(mx0, fmaxf(s[nt][0], s[nt][1]));
            mx1 = fmaxf(mx1, fmaxf(s[nt][2], s[nt][3]));
        }
        mx0 = fmaxf(mx0, __shfl_xor_sync(0xffffffffu, mx0, 1));
        mx0 = fmaxf(mx0, __shfl_xor_sync(0xffffffffu, mx0, 2));
        mx1 = fmaxf(mx1, __shfl_xor_sync(0xffffffffu, mx1, 1));
        mx1 = fmaxf(mx1, __shfl_xor_sync(0xffffffffu, mx1, 2));

        float mn0 = fmaxf(m0, mx0), mn1 = fmaxf(m1, mx1);
        float al0 = exp2f(m0 - mn0), al1 = exp2f(m1 - mn1);
        float sum0 = 0.f, sum1 = 0.f;
#pragma unroll
        for (int nt = 0; nt < 8; nt++) {
            s[nt][0] = exp2f(s[nt][0] - mn0);
            s[nt][1] = exp2f(s[nt][1] - mn0);
            s[nt][2] = exp2f(s[nt][2] - mn1);
            s[nt][3] = exp2f(s[nt][3] - mn1);
            sum0 += s[nt][0] + s[nt][1];
            sum1 += s[nt][2] + s[nt][3];
        }
        sum0 += __shfl_xor_sync(0xffffffffu, sum0, 1);
        sum0 += __shfl_xor_sync(0xffffffffu, sum0, 2);
        sum1 += __shfl_xor_sync(0xffffffffu, sum1, 1);
        sum1 += __shfl_xor_sync(0xffffffffu, sum1, 2);

        l0 = l0 * al0 + sum0;  m0 = mn0;
        l1 = l1 * al1 + sum1;  m1 = mn1;
#pragma unroll
        for (int ct = 0; ct < 8; ct++) {
            o[ct][0] *= al0; o[ct][1] *= al0;
            o[ct][2] *= al1; o[ct][3] *= al1;
        }

        // ---- O += P * V : shuffle C-frag -> A-frag, mma against Vs ----
#pragma unroll
        for (int kt = 0; kt < 8; kt++) {
            float v00 = __shfl_sync(0xffffffffu, s[kt][0], src1);
            float v01 = __shfl_sync(0xffffffffu, s[kt][1], src1);
            float v10 = __shfl_sync(0xffffffffu, s[kt][0], src2);
            float v11 = __shfl_sync(0xffffffffu, s[kt][1], src2);
            float w00 = __shfl_sync(0xffffffffu, s[kt][2], src1);
            float w01 = __shfl_sync(0xffffffffu, s[kt][3], src1);
            float w10 = __shfl_sync(0xffffffffu, s[kt][2], src2);
            float w11 = __shfl_sync(0xffffffffu, s[kt][3], src2);
            float a0 = tf32r(par ? v01 : v00);
            float a1 = tf32r(par ? w01 : w00);
            float a2 = tf32r(par ? v11 : v10);
            float a3 = tf32r(par ? w11 : w10);
#pragma unroll
            for (int ct = 0; ct < 8; ct++) {
                float b0 = Vs[(ct * 8 + r) * STR + kt * 8 + q];
                float b1 = Vs[(ct * 8 + r) * STR + kt * 8 + q + 4];
                mma_tf32(o[ct][0], o[ct][1], o[ct][2], o[ct][3],
                         a0, a1, a2, a3, b0, b1);
            }
        }
        __syncthreads();   // tiles dead; safe to overwrite next iter
    }

    // ---- epilogue: normalize, stage, write g_o transposed [B][C][N] ----
    float il0 = 1.0f / l0, il1 = 1.0f / l1;
    int rb = warp * 16 + r;
#pragma unroll
    for (int ct = 0; ct < 8; ct++) {
        sm[rb * STR + ct * 8 + 2 * q]           = o[ct][0] * il0;
        sm[rb * STR + ct * 8 + 2 * q + 1]       = o[ct][1] * il0;
        sm[(rb + 8) * STR + ct * 8 + 2 * q]     = o[ct][2] * il1;
        sm[(rb + 8) * STR + ct * 8 + 2 * q + 1] = o[ct][3] * il1;
    }
    __syncthreads();
    for (int e = tid; e < 8192; e += 256) {
        int c = e >> 7, n = e & 127;
        g_o[((size_t)b * CDIM + h * HD + c) * NTOK + n0 + n] = sm[n * STR + c];
    }
}

// ---------------- launch ----------------------------------------------------
extern "C" void kernel_launch(void* const* d_in, const int* in_sizes, int n_in,
                              void* d_out, int out_size)
{
    const float* x     = (const float*)d_in[0];
    const float* gamma = (const float*)d_in[1];
    const float* beta  = (const float*)d_in[2];
    const float* Wq    = (const float*)d_in[3];
    const float* bq    = (const float*)d_in[4];
    const float* Wk    = (const float*)d_in[5];
    const float* bk    = (const float*)d_in[6];
    const float* Wv    = (const float*)d_in[7];
    const float* bv    = (const float*)d_in[8];
    const float* Wo    = (const float*)d_in[9];
    const float* bo    = (const float*)d_in[10];
    float* out = (float*)d_out;

    k_transpose<<<dim3(CDIM/32, CDIM/32, 4), dim3(32, 8)>>>(Wq, Wk, Wv, Wo);
    k_groupnorm<<<BATCH * GROUPS, 256>>>(x, gamma, beta);

    dim3 gg(NTOK / 64, CDIM / 64, BATCH);
    k_gemm<<<gg, 256>>>(0, 0, bq, nullptr, nullptr, 0);  // Q  -> g_q  [B][N][C]
    k_gemm<<<gg, 256>>>(0, 1, bk, nullptr, nullptr, 1);  // K  -> g_k  [B][N][C]
    k_gemm<<<gg, 256>>>(0, 2, bv, nullptr, nullptr, 2);  // V  -> g_vt [B][C][N]

    k_attn<<<dim3(NTOK / 128, HEADS, BATCH), 256>>>();

    k_gemm<<<gg, 256>>>(1, 3, bo, x, out, 3);            // out = x + o @ Wo^T + bo
}

// round 3
// speedup vs baseline: 2.2968x; 1.3447x over previous
#include <cuda_runtime.h>
#include <math.h>

#define BATCH  2
#define CDIM   512
#define NTOK   4096
#define HEADS  8
#define HD     64
#define GROUPS 32

// ---------------- scratch (static device globals; no allocations) ----------
__device__ float g_h [(size_t)BATCH*CDIM*NTOK];   // normalized x, layout [B][C][N]
__device__ float g_q [(size_t)BATCH*NTOK*CDIM];   // Q, layout [B][N][C]
__device__ float g_k [(size_t)BATCH*NTOK*CDIM];   // K, layout [B][N][C]
__device__ float g_vt[(size_t)BATCH*CDIM*NTOK];   // V, layout [B][C][N] (transposed)
__device__ float g_o [(size_t)BATCH*CDIM*NTOK];   // attn out, layout [B][C][N]
__device__ float g_wt[4*(size_t)CDIM*CDIM];       // Wq^T, Wk^T, Wv^T, Wo^T : [k][m]

// ---------------- helpers ---------------------------------------------------
__device__ __forceinline__ float tf32r(float x) {
    asm("cvt.rna.tf32.f32 %0, %0;" : "+f"(x));
    return x;
}

__device__ __forceinline__ void mma_tf32(float& d0, float& d1, float& d2, float& d3,
                                         float a0, float a1, float a2, float a3,
                                         float b0, float b1)
{
    asm volatile("mma.sync.aligned.m16n8k8.row.col.f32.tf32.tf32.f32 "
                 "{%0,%1,%2,%3},{%4,%5,%6,%7},{%8,%9},{%0,%1,%2,%3};"
                 : "+f"(d0), "+f"(d1), "+f"(d2), "+f"(d3)
                 : "f"(a0), "f"(a1), "f"(a2), "f"(a3), "f"(b0), "f"(b1));
}

// ---------------- weight transpose: Wt[k][m] = W[m][k] ---------------------
__global__ void k_transpose(const float* __restrict__ W0, const float* __restrict__ W1,
                            const float* __restrict__ W2, const float* __restrict__ W3)
{
    const float* srcs[4] = {W0, W1, W2, W3};
    const float* W = srcs[blockIdx.z];
    float* dst = g_wt + (size_t)blockIdx.z * CDIM * CDIM;

    __shared__ float tile[32][33];
    int x = blockIdx.x * 32 + threadIdx.x;
    int y = blockIdx.y * 32 + threadIdx.y;
#pragma unroll
    for (int i = 0; i < 32; i += 8)
        tile[threadIdx.y + i][threadIdx.x] = W[(size_t)(y + i) * CDIM + x];
    __syncthreads();
    int x2 = blockIdx.y * 32 + threadIdx.x;
    int y2 = blockIdx.x * 32 + threadIdx.y;
#pragma unroll
    for (int i = 0; i < 32; i += 8)
        dst[(size_t)(y2 + i) * CDIM + x2] = tile[threadIdx.x][threadIdx.y + i];
}

// ---------------- GroupNorm: one block per (b, g); region is contiguous ----
__global__ void k_groupnorm(const float* __restrict__ x,
                            const float* __restrict__ gamma,
                            const float* __restrict__ beta)
{
    int b = blockIdx.x >> 5;
    int g = blockIdx.x & 31;
    size_t base = ((size_t)b * CDIM + g * 16) * NTOK;     // 65536 contiguous floats
    const float4* xp = (const float4*)(x + base);
    float4* hp = (float4*)(g_h + base);

    float s = 0.f, ss = 0.f;
    for (int i = threadIdx.x; i < 16384; i += 256) {
        float4 v = xp[i];
        s  += v.x + v.y + v.z + v.w;
        ss += v.x*v.x + v.y*v.y + v.z*v.z + v.w*v.w;
    }
#pragma unroll
    for (int off = 16; off > 0; off >>= 1) {
        s  += __shfl_xor_sync(0xffffffffu, s,  off);
        ss += __shfl_xor_sync(0xffffffffu, ss, off);
    }
    __shared__ float red[18];
    int warp = threadIdx.x >> 5;
    if ((threadIdx.x & 31) == 0) { red[warp] = s; red[8 + warp] = ss; }
    __syncthreads();
    if (threadIdx.x == 0) {
        float S = 0.f, SS = 0.f;
        for (int w = 0; w < 8; w++) { S += red[w]; SS += red[8 + w]; }
        float mean = S * (1.0f / 65536.0f);
        float var  = SS * (1.0f / 65536.0f) - mean * mean;
        red[16] = mean;
        red[17] = rsqrtf(var + 1e-5f);
    }
    __syncthreads();
    float mean = red[16], rstd = red[17];

    for (int i = threadIdx.x; i < 16384; i += 256) {
        int c = g * 16 + (i >> 10);          // element channel (4096 floats / channel)
        float ga = gamma[c] * rstd;
        float be = beta[c] - mean * ga;
        float4 v = xp[i];
        v.x = v.x * ga + be; v.y = v.y * ga + be;
        v.z = v.z * ga + be; v.w = v.w * ga + be;
        hp[i] = v;
    }
}

// ---------------- tf32 mma GEMM: Y[t][c] = sum_k A[k][t] * Wt[k][c] + bias -
// Block tile: 128 tokens x 64 channels, K-tile 32. 8 warps in 4(m) x 2(n),
// each warp computes 32x32 via 2x4 m16n8k8 fragments.
// dst_sel: 0 -> g_q row-major, 1 -> g_k row-major,
//          2 -> g_vt transposed, 3 -> outp transposed + residual
#define ASTR 136   // 128 + 8 : fragment loads hit banks (q*8 + r) -> distinct
#define BSTR 72    // 64  + 8
#define CSTR 65

__global__ void __launch_bounds__(256) k_gemm_mma(int src_sel, int wt_idx,
                                                  const float* __restrict__ bias,
                                                  const float* __restrict__ resid,
                                                  float* __restrict__ outp,
                                                  int dst_sel)
{
    int b  = blockIdx.z;
    int t0 = blockIdx.x * 128;   // token offset
    int c0 = blockIdx.y * 64;    // channel offset

    const float* A  = (src_sel == 0 ? g_h : g_o) + (size_t)b * CDIM * NTOK; // [k][t]
    const float* Wt = g_wt + (size_t)wt_idx * CDIM * CDIM;                  // [k][c]

    __shared__ float sm[128 * CSTR];     // 8320 floats; union of (As,Bs) and Cs
    float* As = sm;                      // [32][ASTR]
    float* Bs = sm + 32 * ASTR;          // [32][BSTR]  (4352 + 2304 = 6656 <= 8320)

    int tid  = threadIdx.x;
    int lane = tid & 31, warp = tid >> 5;
    int r = lane >> 2, q = lane & 3;
    int wm = (warp & 3) * 32;            // warp token offset in tile
    int wn = (warp >> 2) * 32;           // warp channel offset in tile

    float acc[2][4][4];
#pragma unroll
    for (int i = 0; i < 2; i++)
#pragma unroll
        for (int j = 0; j < 4; j++)
#pragma unroll
            for (int k = 0; k < 4; k++) acc[i][j][k] = 0.f;

    int arow = tid >> 3, acl = tid & 7;  // A-tile load coords
    int brow0 = tid >> 4, bcl = tid & 15;

    for (int k0 = 0; k0 < CDIM; k0 += 32) {
        // stage A tile: 32 rows x 128 tokens, coalesced float4
#pragma unroll
        for (int it = 0; it < 4; it++) {
            int col = 4 * (acl + 8 * it);
            float4 v = *(const float4*)&A[(size_t)(k0 + arow) * NTOK + t0 + col];
            As[arow * ASTR + col + 0] = tf32r(v.x);
            As[arow * ASTR + col + 1] = tf32r(v.y);
            As[arow * ASTR + col + 2] = tf32r(v.z);
            As[arow * ASTR + col + 3] = tf32r(v.w);
        }
        // stage B tile: 32 rows x 64 channels
#pragma unroll
        for (int it = 0; it < 2; it++) {
            int row = brow0 + it * 16;
            int col = 4 * bcl;
            float4 v = *(const float4*)&Wt[(size_t)(k0 + row) * CDIM + c0 + col];
            Bs[row * BSTR + col + 0] = tf32r(v.x);
            Bs[row * BSTR + col + 1] = tf32r(v.y);
            Bs[row * BSTR + col + 2] = tf32r(v.z);
            Bs[row * BSTR + col + 3] = tf32r(v.w);
        }
        __syncthreads();

#pragma unroll
        for (int ks = 0; ks < 4; ks++) {
            int k8 = ks * 8;
            float a[2][4], bb[4][2];
#pragma unroll
            for (int ms = 0; ms < 2; ms++) {
                int ml = wm + ms * 16;
                a[ms][0] = As[(k8 + q) * ASTR + ml + r];
                a[ms][1] = As[(k8 + q) * ASTR + ml + r + 8];
                a[ms][2] = As[(k8 + q + 4) * ASTR + ml + r];
                a[ms][3] = As[(k8 + q + 4) * ASTR + ml + r + 8];
            }
#pragma unroll
            for (int ns = 0; ns < 4; ns++) {
                int nl = wn + ns * 8;
                bb[ns][0] = Bs[(k8 + q) * BSTR + nl + r];
                bb[ns][1] = Bs[(k8 + q + 4) * BSTR + nl + r];
            }
#pragma unroll
            for (int ms = 0; ms < 2; ms++)
#pragma unroll
                for (int ns = 0; ns < 4; ns++)
                    mma_tf32(acc[ms][ns][0], acc[ms][ns][1], acc[ms][ns][2], acc[ms][ns][3],
                             a[ms][0], a[ms][1], a[ms][2], a[ms][3],
                             bb[ns][0], bb[ns][1]);
        }
        __syncthreads();
    }

    // bias
#pragma unroll
    for (int ns = 0; ns < 4; ns++) {
        float2 bi = *(const float2*)&bias[c0 + wn + ns * 8 + 2 * q];
#pragma unroll
        for (int ms = 0; ms < 2; ms++) {
            acc[ms][ns][0] += bi.x; acc[ms][ns][1] += bi.y;
            acc[ms][ns][2] += bi.x; acc[ms][ns][3] += bi.y;
        }
    }

    if (dst_sel <= 1) {
        float* Y = (dst_sel == 0 ? g_q : g_k);
#pragma unroll
        for (int ms = 0; ms < 2; ms++) {
            size_t row0 = (size_t)b * NTOK + t0 + wm + ms * 16 + r;
#pragma unroll
            for (int ns = 0; ns < 4; ns++) {
                int ch = c0 + wn + ns * 8 + 2 * q;
                *(float2*)&Y[row0 * CDIM + ch] = make_float2(acc[ms][ns][0], acc[ms][ns][1]);
                *(float2*)&Y[(row0 + 8) * CDIM + ch] = make_float2(acc[ms][ns][2], acc[ms][ns][3]);
            }
        }
    } else {
        // stage into Cs[token][channel], then write transposed [B][C][N]
        float* Cs = sm;
#pragma unroll
        for (int ms = 0; ms < 2; ms++) {
            int rowL = wm + ms * 16 + r;
#pragma unroll
            for (int ns = 0; ns < 4; ns++) {
                int chL = wn + ns * 8 + 2 * q;
                Cs[rowL * CSTR + chL]           = acc[ms][ns][0];
                Cs[rowL * CSTR + chL + 1]       = acc[ms][ns][1];
                Cs[(rowL + 8) * CSTR + chL]     = acc[ms][ns][2];
                Cs[(rowL + 8) * CSTR + chL + 1] = acc[ms][ns][3];
            }
        }
        __syncthreads();
        float* Y = (dst_sel == 2 ? g_vt : outp);
        for (int e = tid; e < 8192; e += 256) {
            int cL = e >> 7, nL = e & 127;
            float v = Cs[nL * CSTR + cL];
            size_t idx = ((size_t)b * CDIM + c0 + cL) * NTOK + t0 + nL;
            if (dst_sel == 3) v += resid[idx];
            Y[idx] = v;
        }
    }
}

// ---------------- attention: flash-style, tf32 mma.sync --------------------
// Block: 128 query rows, 8 warps (warp w owns rows w*16..w*16+15).
// Per j-iter: 64 keys. K tile Ks[j][d], V tile Vs[c][j], both stride 69
// (conflict-free for float4 staging, all fragment loads, and epilogue reads).
#define STR 69

__global__ void __launch_bounds__(256) k_attn()
{
    __shared__ float sm[128 * STR];      // 35328 B union: Qs / (Ks+Vs) / Os
    float* Ks = sm;                      // [64][STR]
    float* Vs = sm + 64 * STR;           // [64][STR]

    int tid  = threadIdx.x;
    int lane = tid & 31, warp = tid >> 5;
    int r = lane >> 2, q = lane & 3;     // quad row / quad col
    int n0 = blockIdx.x * 128;
    int h  = blockIdx.y;
    int b  = blockIdx.z;

    const float SCL = 0.125f * 1.4426950408889634f;  // (1/sqrt(64)) * log2(e)

    // ---- stage Q (pre-scaled, tf32-rounded), then lift to register frags ----
    {
        const float* Qg = g_q + ((size_t)b * NTOK + n0) * CDIM + h * HD;
        int row = tid >> 4, c4 = (tid & 15) << 2;
#pragma unroll
        for (int it = 0; it < 8; it++) {
            int rr = row + it * 16;
            float4 v = *(const float4*)&Qg[(size_t)rr * CDIM + c4];
            sm[rr * STR + c4 + 0] = tf32r(v.x * SCL);
            sm[rr * STR + c4 + 1] = tf32r(v.y * SCL);
            sm[rr * STR + c4 + 2] = tf32r(v.z * SCL);
            sm[rr * STR + c4 + 3] = tf32r(v.w * SCL);
        }
    }
    __syncthreads();

    float aq[8][4];
    {
        int rb = warp * 16 + r;
#pragma unroll
        for (int kt = 0; kt < 8; kt++) {
            int c = kt * 8 + q;
            aq[kt][0] = sm[rb * STR + c];
            aq[kt][1] = sm[(rb + 8) * STR + c];
            aq[kt][2] = sm[rb * STR + c + 4];
            aq[kt][3] = sm[(rb + 8) * STR + c + 4];
        }
    }
    __syncthreads();

    float o[8][4];
#pragma unroll
    for (int i = 0; i < 8; i++)
#pragma unroll
        for (int j = 0; j < 4; j++) o[i][j] = 0.f;
    float m0 = -1e30f, m1 = -1e30f, l0 = 0.f, l1 = 0.f;

    const float* Kg = g_k  + (size_t)b * NTOK * CDIM + h * HD;
    const float* Vg = g_vt + ((size_t)b * CDIM + h * HD) * NTOK;

    int src1 = (lane & ~3) | (q >> 1);
    int src2 = src1 + 2;
    bool par = (q & 1) != 0;

    for (int j0 = 0; j0 < NTOK; j0 += 64) {
        // ---- stage K and V tiles (tf32-rounded) ----
        {
            int row = tid >> 4, c4 = (tid & 15) << 2;
#pragma unroll
            for (int it = 0; it < 4; it++) {
                int rr = row + it * 16;
                float4 kv = *(const float4*)&Kg[(size_t)(j0 + rr) * CDIM + c4];
                Ks[rr * STR + c4 + 0] = tf32r(kv.x);
                Ks[rr * STR + c4 + 1] = tf32r(kv.y);
                Ks[rr * STR + c4 + 2] = tf32r(kv.z);
                Ks[rr * STR + c4 + 3] = tf32r(kv.w);
                float4 vv = *(const float4*)&Vg[(size_t)rr * NTOK + j0 + c4];
                Vs[rr * STR + c4 + 0] = tf32r(vv.x);
                Vs[rr * STR + c4 + 1] = tf32r(vv.y);
                Vs[rr * STR + c4 + 2] = tf32r(vv.z);
                Vs[rr * STR + c4 + 3] = tf32r(vv.w);
            }
        }
        __syncthreads();

        // ---- S = Q * K^T (already in log2 space; Q pre-scaled) ----
        float s[8][4];
#pragma unroll
        for (int i = 0; i < 8; i++)
#pragma unroll
            for (int j = 0; j < 4; j++) s[i][j] = 0.f;

#pragma unroll
        for (int kt = 0; kt < 8; kt++) {
#pragma unroll
            for (int nt = 0; nt < 8; nt++) {
                float b0 = Ks[(nt * 8 + r) * STR + kt * 8 + q];
                float b1 = Ks[(nt * 8 + r) * STR + kt * 8 + q + 4];
                mma_tf32(s[nt][0], s[nt][1], s[nt][2], s[nt][3],
                         aq[kt][0], aq[kt][1], aq[kt][2], aq[kt][3], b0, b1);
            }
        }

        // ---- online softmax (base-2); rows live in quads ----
        float mx0 = -1e30f, mx1 = -1e30f;
#pragma unroll
        for (int nt = 0; nt < 8; nt++) {
            mx0 = fmaxf(mx0, fmaxf(s[nt][0], s[nt][1]));
            mx1 = fmaxf(mx1, fmaxf(s[nt][2], s[nt][3]));
        }
        mx0 = fmaxf(mx0, __shfl_xor_sync(0xffffffffu, mx0, 1));
        mx0 = fmaxf(mx0, __shfl_xor_sync(0xffffffffu, mx0, 2));
        mx1 = fmaxf(mx1, __shfl_xor_sync(0xffffffffu, mx1, 1));
        mx1 = fmaxf(mx1, __shfl_xor_sync(0xffffffffu, mx1, 2));

        float mn0 = fmaxf(m0, mx0), mn1 = fmaxf(m1, mx1);
        float al0 = exp2f(m0 - mn0), al1 = exp2f(m1 - mn1);
        float sum0 = 0.f, sum1 = 0.f;
#pragma unroll
        for (int nt = 0; nt < 8; nt++) {
            s[nt][0] = exp2f(s[nt][0] - mn0);
            s[nt][1] = exp2f(s[nt][1] - mn0);
            s[nt][2] = exp2f(s[nt][2] - mn1);
            s[nt][3] = exp2f(s[nt][3] - mn1);
            sum0 += s[nt][0] + s[nt][1];
            sum1 += s[nt][2] + s[nt][3];
        }
        sum0 += __shfl_xor_sync(0xffffffffu, sum0, 1);
        sum0 += __shfl_xor_sync(0xffffffffu, sum0, 2);
        sum1 += __shfl_xor_sync(0xffffffffu, sum1, 1);
        sum1 += __shfl_xor_sync(0xffffffffu, sum1, 2);

        l0 = l0 * al0 + sum0;  m0 = mn0;
        l1 = l1 * al1 + sum1;  m1 = mn1;
#pragma unroll
        for (int ct = 0; ct < 8; ct++) {
            o[ct][0] *= al0; o[ct][1] *= al0;
            o[ct][2] *= al1; o[ct][3] *= al1;
        }

        // ---- O += P * V : shuffle C-frag -> A-frag, mma against Vs ----
#pragma unroll
        for (int kt = 0; kt < 8; kt++) {
            float v00 = __shfl_sync(0xffffffffu, s[kt][0], src1);
            float v01 = __shfl_sync(0xffffffffu, s[kt][1], src1);
            float v10 = __shfl_sync(0xffffffffu, s[kt][0], src2);
            float v11 = __shfl_sync(0xffffffffu, s[kt][1], src2);
            float w00 = __shfl_sync(0xffffffffu, s[kt][2], src1);
            float w01 = __shfl_sync(0xffffffffu, s[kt][3], src1);
            float w10 = __shfl_sync(0xffffffffu, s[kt][2], src2);
            float w11 = __shfl_sync(0xffffffffu, s[kt][3], src2);
            float a0 = tf32r(par ? v01 : v00);
            float a1 = tf32r(par ? w01 : w00);
            float a2 = tf32r(par ? v11 : v10);
            float a3 = tf32r(par ? w11 : w10);
#pragma unroll
            for (int ct = 0; ct < 8; ct++) {
                float b0 = Vs[(ct * 8 + r) * STR + kt * 8 + q];
                float b1 = Vs[(ct * 8 + r) * STR + kt * 8 + q + 4];
                mma_tf32(o[ct][0], o[ct][1], o[ct][2], o[ct][3],
                         a0, a1, a2, a3, b0, b1);
            }
        }
        __syncthreads();   // tiles dead; safe to overwrite next iter
    }

    // ---- epilogue: normalize, stage, write g_o transposed [B][C][N] ----
    float il0 = 1.0f / l0, il1 = 1.0f / l1;
    int rb = warp * 16 + r;
#pragma unroll
    for (int ct = 0; ct < 8; ct++) {
        sm[rb * STR + ct * 8 + 2 * q]           = o[ct][0] * il0;
        sm[rb * STR + ct * 8 + 2 * q + 1]       = o[ct][1] * il0;
        sm[(rb + 8) * STR + ct * 8 + 2 * q]     = o[ct][2] * il1;
        sm[(rb + 8) * STR + ct * 8 + 2 * q + 1] = o[ct][3] * il1;
    }
    __syncthreads();
    for (int e = tid; e < 8192; e += 256) {
        int c = e >> 7, n = e & 127;
        g_o[((size_t)b * CDIM + h * HD + c) * NTOK + n0 + n] = sm[n * STR + c];
    }
}

// ---------------- launch ----------------------------------------------------
extern "C" void kernel_launch(void* const* d_in, const int* in_sizes, int n_in,
                              void* d_out, int out_size)
{
    const float* x     = (const float*)d_in[0];
    const float* gamma = (const float*)d_in[1];
    const float* beta  = (const float*)d_in[2];
    const float* Wq    = (const float*)d_in[3];
    const float* bq    = (const float*)d_in[4];
    const float* Wk    = (const float*)d_in[5];
    const float* bk    = (const float*)d_in[6];
    const float* Wv    = (const float*)d_in[7];
    const float* bv    = (const float*)d_in[8];
    const float* Wo    = (const float*)d_in[9];
    const float* bo    = (const float*)d_in[10];
    float* out = (float*)d_out;

    k_transpose<<<dim3(CDIM/32, CDIM/32, 4), dim3(32, 8)>>>(Wq, Wk, Wv, Wo);
    k_groupnorm<<<BATCH * GROUPS, 256>>>(x, gamma, beta);

    dim3 gg(NTOK / 128, CDIM / 64, BATCH);
    k_gemm_mma<<<gg, 256>>>(0, 0, bq, nullptr, nullptr, 0);  // Q  -> g_q  [B][N][C]
    k_gemm_mma<<<gg, 256>>>(0, 1, bk, nullptr, nullptr, 1);  // K  -> g_k  [B][N][C]
    k_gemm_mma<<<gg, 256>>>(0, 2, bv, nullptr, nullptr, 2);  // V  -> g_vt [B][C][N]

    k_attn<<<dim3(NTOK / 128, HEADS, BATCH), 256>>>();

    k_gemm_mma<<<gg, 256>>>(1, 3, bo, x, out, 3);            // out = x + o @ Wo^T + bo
}

// round 4
// speedup vs baseline: 4.5528x; 1.9822x over previous
#include <cuda_runtime.h>
#include <cuda_bf16.h>
#include <math.h>

#define BATCH  2
#define CDIM   512
#define NTOK   4096
#define HEADS  8
#define HD     64
#define GROUPS 32

// ---------------- scratch (static device globals; no allocations) ----------
__device__ float g_h [(size_t)BATCH*CDIM*NTOK];            // normalized x, [B][C][N]
__device__ __nv_bfloat16 g_qb[(size_t)BATCH*NTOK*CDIM];    // Q (pre-scaled), [B][N][C]
__device__ __nv_bfloat16 g_kb[(size_t)BATCH*NTOK*CDIM];    // K, [B][N][C]
__device__ __nv_bfloat16 g_vb[(size_t)BATCH*CDIM*NTOK];    // V, [B][C][N]
__device__ float g_o [(size_t)BATCH*CDIM*NTOK];            // attn out, [B][C][N]
__device__ float g_wt[4*(size_t)CDIM*CDIM];                // W^T x4 : [k][m]

// ---------------- helpers ---------------------------------------------------
__device__ __forceinline__ float tf32r(float x) {
    asm("cvt.rna.tf32.f32 %0, %0;" : "+f"(x));
    return x;
}

__device__ __forceinline__ void mma_tf32(float& d0, float& d1, float& d2, float& d3,
                                         float a0, float a1, float a2, float a3,
                                         float b0, float b1)
{
    asm volatile("mma.sync.aligned.m16n8k8.row.col.f32.tf32.tf32.f32 "
                 "{%0,%1,%2,%3},{%4,%5,%6,%7},{%8,%9},{%0,%1,%2,%3};"
                 : "+f"(d0), "+f"(d1), "+f"(d2), "+f"(d3)
                 : "f"(a0), "f"(a1), "f"(a2), "f"(a3), "f"(b0), "f"(b1));
}

__device__ __forceinline__ void mma_bf16(float& d0, float& d1, float& d2, float& d3,
                                         unsigned a0, unsigned a1, unsigned a2, unsigned a3,
                                         unsigned b0, unsigned b1)
{
    asm volatile("mma.sync.aligned.m16n8k16.row.col.f32.bf16.bf16.f32 "
                 "{%0,%1,%2,%3},{%4,%5,%6,%7},{%8,%9},{%0,%1,%2,%3};"
                 : "+f"(d0), "+f"(d1), "+f"(d2), "+f"(d3)
                 : "r"(a0), "r"(a1), "r"(a2), "r"(a3), "r"(b0), "r"(b1));
}

__device__ __forceinline__ unsigned packbf(float lo, float hi) {
    __nv_bfloat162 p = __floats2bfloat162_rn(lo, hi);
    return *(unsigned*)&p;
}

// ---------------- weight transpose: Wt[k][m] = W[m][k] ---------------------
__global__ void k_transpose(const float* __restrict__ W0, const float* __restrict__ W1,
                            const float* __restrict__ W2, const float* __restrict__ W3)
{
    const float* srcs[4] = {W0, W1, W2, W3};
    const float* W = srcs[blockIdx.z];
    float* dst = g_wt + (size_t)blockIdx.z * CDIM * CDIM;

    __shared__ float tile[32][33];
    int x = blockIdx.x * 32 + threadIdx.x;
    int y = blockIdx.y * 32 + threadIdx.y;
#pragma unroll
    for (int i = 0; i < 32; i += 8)
        tile[threadIdx.y + i][threadIdx.x] = W[(size_t)(y + i) * CDIM + x];
    __syncthreads();
    int x2 = blockIdx.y * 32 + threadIdx.x;
    int y2 = blockIdx.x * 32 + threadIdx.y;
#pragma unroll
    for (int i = 0; i < 32; i += 8)
        dst[(size_t)(y2 + i) * CDIM + x2] = tile[threadIdx.x][threadIdx.y + i];
}

// ---------------- GroupNorm: one block per (b, g); region is contiguous ----
__global__ void k_groupnorm(const float* __restrict__ x,
                            const float* __restrict__ gamma,
                            const float* __restrict__ beta)
{
    int b = blockIdx.x >> 5;
    int g = blockIdx.x & 31;
    size_t base = ((size_t)b * CDIM + g * 16) * NTOK;
    const float4* xp = (const float4*)(x + base);
    float4* hp = (float4*)(g_h + base);

    float s = 0.f, ss = 0.f;
    for (int i = threadIdx.x; i < 16384; i += 256) {
        float4 v = xp[i];
        s  += v.x + v.y + v.z + v.w;
        ss += v.x*v.x + v.y*v.y + v.z*v.z + v.w*v.w;
    }
#pragma unroll
    for (int off = 16; off > 0; off >>= 1) {
        s  += __shfl_xor_sync(0xffffffffu, s,  off);
        ss += __shfl_xor_sync(0xffffffffu, ss, off);
    }
    __shared__ float red[18];
    int warp = threadIdx.x >> 5;
    if ((threadIdx.x & 31) == 0) { red[warp] = s; red[8 + warp] = ss; }
    __syncthreads();
    if (threadIdx.x == 0) {
        float S = 0.f, SS = 0.f;
        for (int w = 0; w < 8; w++) { S += red[w]; SS += red[8 + w]; }
        float mean = S * (1.0f / 65536.0f);
        float var  = SS * (1.0f / 65536.0f) - mean * mean;
        red[16] = mean;
        red[17] = rsqrtf(var + 1e-5f);
    }
    __syncthreads();
    float mean = red[16], rstd = red[17];

    for (int i = threadIdx.x; i < 16384; i += 256) {
        int c = g * 16 + (i >> 10);
        float ga = gamma[c] * rstd;
        float be = beta[c] - mean * ga;
        float4 v = xp[i];
        v.x = v.x * ga + be; v.y = v.y * ga + be;
        v.z = v.z * ga + be; v.w = v.w * ga + be;
        hp[i] = v;
    }
}

// ---------------- tf32 mma GEMM: Y[t][c] = sum_k A[k][t] * Wt[k][c] + bias -
// dst_sel: 0 -> g_qb bf16 row (scaled), 1 -> g_kb bf16 row,
//          2 -> g_vb bf16 transposed, 3 -> outp f32 transposed + residual
#define ASTR 136
#define BSTR 72
#define CSTR 65

__global__ void __launch_bounds__(256) k_gemm_mma(int src_sel, int wt_idx,
                                                  const float* __restrict__ bias,
                                                  const float* __restrict__ resid,
                                                  float* __restrict__ outp,
                                                  int dst_sel, float oscale)
{
    int b  = blockIdx.z;
    int t0 = blockIdx.x * 128;
    int c0 = blockIdx.y * 64;

    const float* A  = (src_sel == 0 ? g_h : g_o) + (size_t)b * CDIM * NTOK; // [k][t]
    const float* Wt = g_wt + (size_t)wt_idx * CDIM * CDIM;                  // [k][c]

    __shared__ float sm[128 * CSTR];
    float* As = sm;
    float* Bs = sm + 32 * ASTR;

    int tid  = threadIdx.x;
    int lane = tid & 31, warp = tid >> 5;
    int r = lane >> 2, q = lane & 3;
    int wm = (warp & 3) * 32;
    int wn = (warp >> 2) * 32;

    float acc[2][4][4];
#pragma unroll
    for (int i = 0; i < 2; i++)
#pragma unroll
        for (int j = 0; j < 4; j++)
#pragma unroll
            for (int k = 0; k < 4; k++) acc[i][j][k] = 0.f;

    int arow = tid >> 3, acl = tid & 7;
    int brow0 = tid >> 4, bcl = tid & 15;

    for (int k0 = 0; k0 < CDIM; k0 += 32) {
#pragma unroll
        for (int it = 0; it < 4; it++) {
            int col = 4 * (acl + 8 * it);
            float4 v = *(const float4*)&A[(size_t)(k0 + arow) * NTOK + t0 + col];
            As[arow * ASTR + col + 0] = tf32r(v.x);
            As[arow * ASTR + col + 1] = tf32r(v.y);
            As[arow * ASTR + col + 2] = tf32r(v.z);
            As[arow * ASTR + col + 3] = tf32r(v.w);
        }
#pragma unroll
        for (int it = 0; it < 2; it++) {
            int row = brow0 + it * 16;
            int col = 4 * bcl;
            float4 v = *(const float4*)&Wt[(size_t)(k0 + row) * CDIM + c0 + col];
            Bs[row * BSTR + col + 0] = tf32r(v.x);
            Bs[row * BSTR + col + 1] = tf32r(v.y);
            Bs[row * BSTR + col + 2] = tf32r(v.z);
            Bs[row * BSTR + col + 3] = tf32r(v.w);
        }
        __syncthreads();

#pragma unroll
        for (int ks = 0; ks < 4; ks++) {
            int k8 = ks * 8;
            float a[2][4], bb[4][2];
#pragma unroll
            for (int ms = 0; ms < 2; ms++) {
                int ml = wm + ms * 16;
                a[ms][0] = As[(k8 + q) * ASTR + ml + r];
                a[ms][1] = As[(k8 + q) * ASTR + ml + r + 8];
                a[ms][2] = As[(k8 + q + 4) * ASTR + ml + r];
                a[ms][3] = As[(k8 + q + 4) * ASTR + ml + r + 8];
            }
#pragma unroll
            for (int ns = 0; ns < 4; ns++) {
                int nl = wn + ns * 8;
                bb[ns][0] = Bs[(k8 + q) * BSTR + nl + r];
                bb[ns][1] = Bs[(k8 + q + 4) * BSTR + nl + r];
            }
#pragma unroll
            for (int ms = 0; ms < 2; ms++)
#pragma unroll
                for (int ns = 0; ns < 4; ns++)
                    mma_tf32(acc[ms][ns][0], acc[ms][ns][1], acc[ms][ns][2], acc[ms][ns][3],
                             a[ms][0], a[ms][1], a[ms][2], a[ms][3],
                             bb[ns][0], bb[ns][1]);
        }
        __syncthreads();
    }

#pragma unroll
    for (int ns = 0; ns < 4; ns++) {
        float2 bi = *(const float2*)&bias[c0 + wn + ns * 8 + 2 * q];
#pragma unroll
        for (int ms = 0; ms < 2; ms++) {
            acc[ms][ns][0] += bi.x; acc[ms][ns][1] += bi.y;
            acc[ms][ns][2] += bi.x; acc[ms][ns][3] += bi.y;
        }
    }

    if (dst_sel <= 1) {
        __nv_bfloat16* Y = (dst_sel == 0 ? g_qb : g_kb);
#pragma unroll
        for (int ms = 0; ms < 2; ms++) {
            size_t row0 = (size_t)b * NTOK + t0 + wm + ms * 16 + r;
#pragma unroll
            for (int ns = 0; ns < 4; ns++) {
                int ch = c0 + wn + ns * 8 + 2 * q;
                *(__nv_bfloat162*)&Y[row0 * CDIM + ch] =
                    __floats2bfloat162_rn(acc[ms][ns][0] * oscale, acc[ms][ns][1] * oscale);
                *(__nv_bfloat162*)&Y[(row0 + 8) * CDIM + ch] =
                    __floats2bfloat162_rn(acc[ms][ns][2] * oscale, acc[ms][ns][3] * oscale);
            }
        }
    } else {
        float* Cs = sm;
#pragma unroll
        for (int ms = 0; ms < 2; ms++) {
            int rowL = wm + ms * 16 + r;
#pragma unroll
            for (int ns = 0; ns < 4; ns++) {
                int chL = wn + ns * 8 + 2 * q;
                Cs[rowL * CSTR + chL]           = acc[ms][ns][0];
                Cs[rowL * CSTR + chL + 1]       = acc[ms][ns][1];
                Cs[(rowL + 8) * CSTR + chL]     = acc[ms][ns][2];
                Cs[(rowL + 8) * CSTR + chL + 1] = acc[ms][ns][3];
            }
        }
        __syncthreads();
        if (dst_sel == 2) {
            for (int e = tid; e < 8192; e += 256) {
                int cL = e >> 7, nL = e & 127;
                size_t idx = ((size_t)b * CDIM + c0 + cL) * NTOK + t0 + nL;
                g_vb[idx] = __float2bfloat16(Cs[nL * CSTR + cL]);
            }
        } else {
            for (int e = tid; e < 8192; e += 256) {
                int cL = e >> 7, nL = e & 127;
                size_t idx = ((size_t)b * CDIM + c0 + cL) * NTOK + t0 + nL;
                outp[idx] = Cs[nL * CSTR + cL] + resid[idx];
            }
        }
    }
}

// ---------------- attention: flash-style, bf16 m16n8k16 --------------------
// Block: 128 query rows, 8 warps (warp w owns rows w*16..w*16+15).
// Per j-iter: 64 keys. Ks[key][72] bf16, Vs[c][72] bf16 (j contiguous).
// All fragment loads are LDS.32 (bf16 pairs), conflict-free at stride 36 words.
#define KW 36   // row stride in 32-bit words (72 bf16)

__global__ void __launch_bounds__(256) k_attn()
{
    __shared__ __align__(16) unsigned char smraw[18432];
    unsigned* Kw = (unsigned*)smraw;                 // [64][KW]
    unsigned* Vw = (unsigned*)(smraw + 9216);        // [64][KW]
    unsigned* Qw = (unsigned*)smraw;                 // [128][KW] (pre-loop only)
    float*    Es = (float*)smraw;                    // [64][71]  (epilogue only)

    int tid  = threadIdx.x;
    int lane = tid & 31, warp = tid >> 5;
    int r = lane >> 2, q = lane & 3;
    int n0 = blockIdx.x * 128;
    int h  = blockIdx.y;
    int b  = blockIdx.z;

    // ---- stage Q (already bf16, already scaled by log2e/8 in GEMM) ----
    {
        const __nv_bfloat16* Qg = g_qb + ((size_t)b * NTOK + n0) * CDIM + h * HD;
        int row = tid >> 1, s = tid & 1;
#pragma unroll
        for (int it = 0; it < 4; it++) {
            int col = 8 * (4 * s + it);                        // bf16 units
            uint4 v = *(const uint4*)&Qg[(size_t)row * CDIM + col];
            *(uint4*)&Qw[row * KW + (col >> 1)] = v;
        }
    }
    __syncthreads();

    unsigned aq[4][4];
    {
        int rb = warp * 16 + r;
#pragma unroll
        for (int kt = 0; kt < 4; kt++) {
            int base = kt * 8 + q;
            aq[kt][0] = Qw[rb * KW + base];
            aq[kt][1] = Qw[(rb + 8) * KW + base];
            aq[kt][2] = Qw[rb * KW + base + 4];
            aq[kt][3] = Qw[(rb + 8) * KW + base + 4];
        }
    }
    __syncthreads();

    float o[8][4];
#pragma unroll
    for (int i = 0; i < 8; i++)
#pragma unroll
        for (int j = 0; j < 4; j++) o[i][j] = 0.f;
    float m0 = -1e30f, m1 = -1e30f, l0 = 0.f, l1 = 0.f;

    const __nv_bfloat16* Kg = g_kb + (size_t)b * NTOK * CDIM + h * HD;
    const __nv_bfloat16* Vg = g_vb + ((size_t)b * CDIM + h * HD) * NTOK;

    int srow = tid >> 2, sseg = tid & 3;   // staging coords: 64 rows x 4 segs

    for (int j0 = 0; j0 < NTOK; j0 += 64) {
        // ---- stage K tile [64 keys][64 d] and V tile [64 c][64 j] ----
        {
            int col = sseg * 16;                               // bf16 units
            uint4 k0v = *(const uint4*)&Kg[(size_t)(j0 + srow) * CDIM + col];
            uint4 k1v = *(const uint4*)&Kg[(size_t)(j0 + srow) * CDIM + col + 8];
            *(uint4*)&Kw[srow * KW + sseg * 8]     = k0v;
            *(uint4*)&Kw[srow * KW + sseg * 8 + 4] = k1v;
            uint4 v0v = *(const uint4*)&Vg[(size_t)srow * NTOK + j0 + col];
            uint4 v1v = *(const uint4*)&Vg[(size_t)srow * NTOK + j0 + col + 8];
            *(uint4*)&Vw[srow * KW + sseg * 8]     = v0v;
            *(uint4*)&Vw[srow * KW + sseg * 8 + 4] = v1v;
        }
        __syncthreads();

        // ---- S = Q * K^T (log2 space) ----
        float s[8][4];
#pragma unroll
        for (int i = 0; i < 8; i++)
#pragma unroll
            for (int j = 0; j < 4; j++) s[i][j] = 0.f;

#pragma unroll
        for (int kt = 0; kt < 4; kt++) {
#pragma unroll
            for (int nt = 0; nt < 8; nt++) {
                unsigned b0 = Kw[(nt * 8 + r) * KW + kt * 8 + q];
                unsigned b1 = Kw[(nt * 8 + r) * KW + kt * 8 + q + 4];
                mma_bf16(s[nt][0], s[nt][1], s[nt][2], s[nt][3],
                         aq[kt][0], aq[kt][1], aq[kt][2], aq[kt][3], b0, b1);
            }
        }

        // ---- online softmax (base-2); rows reduced across 4 q-lanes ----
        float mx0 = -1e30f, mx1 = -1e30f;
#pragma unroll
        for (int nt = 0; nt < 8; nt++) {
            mx0 = fmaxf(mx0, fmaxf(s[nt][0], s[nt][1]));
            mx1 = fmaxf(mx1, fmaxf(s[nt][2], s[nt][3]));
        }
        mx0 = fmaxf(mx0, __shfl_xor_sync(0xffffffffu, mx0, 1));
        mx0 = fmaxf(mx0, __shfl_xor_sync(0xffffffffu, mx0, 2));
        mx1 = fmaxf(mx1, __shfl_xor_sync(0xffffffffu, mx1, 1));
        mx1 = fmaxf(mx1, __shfl_xor_sync(0xffffffffu, mx1, 2));

        float mn0 = fmaxf(m0, mx0), mn1 = fmaxf(m1, mx1);
        float al0 = exp2f(m0 - mn0), al1 = exp2f(m1 - mn1);
        float sum0 = 0.f, sum1 = 0.f;
#pragma unroll
        for (int nt = 0; nt < 8; nt++) {
            s[nt][0] = exp2f(s[nt][0] - mn0);
            s[nt][1] = exp2f(s[nt][1] - mn0);
            s[nt][2] = exp2f(s[nt][2] - mn1);
            s[nt][3] = exp2f(s[nt][3] - mn1);
            sum0 += s[nt][0] + s[nt][1];
            sum1 += s[nt][2] + s[nt][3];
        }
        sum0 += __shfl_xor_sync(0xffffffffu, sum0, 1);
        sum0 += __shfl_xor_sync(0xffffffffu, sum0, 2);
        sum1 += __shfl_xor_sync(0xffffffffu, sum1, 1);
        sum1 += __shfl_xor_sync(0xffffffffu, sum1, 2);

        l0 = l0 * al0 + sum0;  m0 = mn0;
        l1 = l1 * al1 + sum1;  m1 = mn1;
#pragma unroll
        for (int ct = 0; ct < 8; ct++) {
            o[ct][0] *= al0; o[ct][1] *= al0;
            o[ct][2] *= al1; o[ct][3] *= al1;
        }

        // ---- O += P * V : C-frag -> bf16 A-frag is a pure pack (no shfl) ----
#pragma unroll
        for (int kt = 0; kt < 4; kt++) {
            unsigned a0 = packbf(s[2*kt][0],     s[2*kt][1]);
            unsigned a1 = packbf(s[2*kt][2],     s[2*kt][3]);
            unsigned a2 = packbf(s[2*kt + 1][0], s[2*kt + 1][1]);
            unsigned a3 = packbf(s[2*kt + 1][2], s[2*kt + 1][3]);
#pragma unroll
            for (int ct = 0; ct < 8; ct++) {
                unsigned b0 = Vw[(ct * 8 + r) * KW + kt * 8 + q];
                unsigned b1 = Vw[(ct * 8 + r) * KW + kt * 8 + q + 4];
                mma_bf16(o[ct][0], o[ct][1], o[ct][2], o[ct][3],
                         a0, a1, a2, a3, b0, b1);
            }
        }
        __syncthreads();
    }

    // ---- epilogue: normalize, two-phase smem transpose, write [B][C][N] ----
    float il0 = 1.0f / l0, il1 = 1.0f / l1;
#pragma unroll
    for (int ph = 0; ph < 2; ph++) {
        if ((warp >> 2) == ph) {
            int rowL = (warp & 3) * 16 + r;
#pragma unroll
            for (int ct = 0; ct < 8; ct++) {
                int cc = ct * 8 + 2 * q;
                Es[rowL * 71 + cc]           = o[ct][0] * il0;
                Es[rowL * 71 + cc + 1]       = o[ct][1] * il0;
                Es[(rowL + 8) * 71 + cc]     = o[ct][2] * il1;
                Es[(rowL + 8) * 71 + cc + 1] = o[ct][3] * il1;
            }
        }
        __syncthreads();
        for (int e = tid; e < 4096; e += 256) {
            int c = e >> 6, n = e & 63;
            g_o[((size_t)b * CDIM + h * HD + c) * NTOK + n0 + ph * 64 + n] = Es[n * 71 + c];
        }
        __syncthreads();
    }
}

// ---------------- launch ----------------------------------------------------
extern "C" void kernel_launch(void* const* d_in, const int* in_sizes, int n_in,
                              void* d_out, int out_size)
{
    const float* x     = (const float*)d_in[0];
    const float* gamma = (const float*)d_in[1];
    const float* beta  = (const float*)d_in[2];
    const float* Wq    = (const float*)d_in[3];
    const float* bq    = (const float*)d_in[4];
    const float* Wk    = (const float*)d_in[5];
    const float* bk    = (const float*)d_in[6];
    const float* Wv    = (const float*)d_in[7];
    const float* bv    = (const float*)d_in[8];
    const float* Wo    = (const float*)d_in[9];
    const float* bo    = (const float*)d_in[10];
    float* out = (float*)d_out;

    const float SCL = 0.125f * 1.4426950408889634f;   // (1/sqrt(hd)) * log2(e)

    k_transpose<<<dim3(CDIM/32, CDIM/32, 4), dim3(32, 8)>>>(Wq, Wk, Wv, Wo);
    k_groupnorm<<<BATCH * GROUPS, 256>>>(x, gamma, beta);

    dim3 gg(NTOK / 128, CDIM / 64, BATCH);
    k_gemm_mma<<<gg, 256>>>(0, 0, bq, nullptr, nullptr, 0, SCL);   // Q -> g_qb
    k_gemm_mma<<<gg, 256>>>(0, 1, bk, nullptr, nullptr, 1, 1.0f);  // K -> g_kb
    k_gemm_mma<<<gg, 256>>>(0, 2, bv, nullptr, nullptr, 2, 1.0f);  // V -> g_vb

    k_attn<<<dim3(NTOK / 128, HEADS, BATCH), 256>>>();

    k_gemm_mma<<<gg, 256>>>(1, 3, bo, x, out, 3, 1.0f);            // out = x + o@Wo^T + bo
}

// round 5
// speedup vs baseline: 4.9218x; 1.0810x over previous
#include <cuda_runtime.h>
#include <cuda_bf16.h>
#include <math.h>

#define BATCH  2
#define CDIM   512
#define NTOK   4096
#define HEADS  8
#define HD     64
#define GROUPS 32

// ---------------- scratch (static device globals; no allocations) ----------
__device__ __nv_bfloat16 g_hb[(size_t)BATCH*NTOK*CDIM];   // GN out, [B][N][C]
__device__ __nv_bfloat16 g_qb[(size_t)BATCH*NTOK*CDIM];   // Q (pre-scaled), [B][N][C]
__device__ __nv_bfloat16 g_kb[(size_t)BATCH*NTOK*CDIM];   // K, [B][N][C]
__device__ __nv_bfloat16 g_vb[(size_t)BATCH*CDIM*NTOK];   // V, [B][C][N]
__device__ float g_o [(size_t)BATCH*CDIM*NTOK];           // attn out, [B][C][N]
__device__ float g_wt[(size_t)CDIM*CDIM];                 // Wo^T fp32 [k][m]
__device__ __nv_bfloat16 g_wb[3*(size_t)CDIM*CDIM];       // Wq,Wk,Wv bf16 [c][k]

// ---------------- helpers ---------------------------------------------------
__device__ __forceinline__ float tf32r(float x) {
    asm("cvt.rna.tf32.f32 %0, %0;" : "+f"(x));
    return x;
}

__device__ __forceinline__ void mma_tf32(float& d0, float& d1, float& d2, float& d3,
                                         float a0, float a1, float a2, float a3,
                                         float b0, float b1)
{
    asm volatile("mma.sync.aligned.m16n8k8.row.col.f32.tf32.tf32.f32 "
                 "{%0,%1,%2,%3},{%4,%5,%6,%7},{%8,%9},{%0,%1,%2,%3};"
                 : "+f"(d0), "+f"(d1), "+f"(d2), "+f"(d3)
                 : "f"(a0), "f"(a1), "f"(a2), "f"(a3), "f"(b0), "f"(b1));
}

__device__ __forceinline__ void mma_bf16(float& d0, float& d1, float& d2, float& d3,
                                         unsigned a0, unsigned a1, unsigned a2, unsigned a3,
                                         unsigned b0, unsigned b1)
{
    asm volatile("mma.sync.aligned.m16n8k16.row.col.f32.bf16.bf16.f32 "
                 "{%0,%1,%2,%3},{%4,%5,%6,%7},{%8,%9},{%0,%1,%2,%3};"
                 : "+f"(d0), "+f"(d1), "+f"(d2), "+f"(d3)
                 : "r"(a0), "r"(a1), "r"(a2), "r"(a3), "r"(b0), "r"(b1));
}

__device__ __forceinline__ unsigned packbf(float lo, float hi) {
    __nv_bfloat162 p = __floats2bfloat162_rn(lo, hi);
    return *(unsigned*)&p;
}

__device__ __forceinline__ void cpa16(unsigned dst, const void* src) {
    asm volatile("cp.async.ca.shared.global [%0], [%1], 16;" :: "r"(dst), "l"(src));
}
#define CP_COMMIT() asm volatile("cp.async.commit_group;")
#define CP_WAIT1()  asm volatile("cp.async.wait_group 1;")

// ---------------- weight prep ------------------------------------------------
// bf16 copies of Wq/Wk/Wv in native [c][k] layout
__global__ void k_wconv(const float* __restrict__ W0, const float* __restrict__ W1,
                        const float* __restrict__ W2)
{
    const float* srcs[3] = {W0, W1, W2};
    const float* W = srcs[blockIdx.y];
    __nv_bfloat16* dst = g_wb + (size_t)blockIdx.y * CDIM * CDIM;
    size_t i2 = ((size_t)blockIdx.x * 256 + threadIdx.x) * 2;
    float2 v = *(const float2*)&W[i2];
    *(__nv_bfloat162*)&dst[i2] = __floats2bfloat162_rn(v.x, v.y);
}

// Wo transpose (fp32): g_wt[k][m] = Wo[m][k]
__global__ void k_transpose(const float* __restrict__ W)
{
    __shared__ float tile[32][33];
    int x = blockIdx.x * 32 + threadIdx.x;
    int y = blockIdx.y * 32 + threadIdx.y;
#pragma unroll
    for (int i = 0; i < 32; i += 8)
        tile[threadIdx.y + i][threadIdx.x] = W[(size_t)(y + i) * CDIM + x];
    __syncthreads();
    int x2 = blockIdx.y * 32 + threadIdx.x;
    int y2 = blockIdx.x * 32 + threadIdx.y;
#pragma unroll
    for (int i = 0; i < 32; i += 8)
        g_wt[(size_t)(y2 + i) * CDIM + x2] = tile[threadIdx.x][threadIdx.y + i];
}

// ---------------- GroupNorm: one block per (b, g); writes bf16 [B][N][C] ----
__global__ void k_groupnorm(const float* __restrict__ x,
                            const float* __restrict__ gamma,
                            const float* __restrict__ beta)
{
    int b = blockIdx.x >> 5;
    int g = blockIdx.x & 31;
    size_t base = ((size_t)b * CDIM + g * 16) * NTOK;     // 65536 contiguous floats
    const float4* xp = (const float4*)(x + base);

    float s = 0.f, ss = 0.f;
    for (int i = threadIdx.x; i < 16384; i += 256) {
        float4 v = xp[i];
        s  += v.x + v.y + v.z + v.w;
        ss += v.x*v.x + v.y*v.y + v.z*v.z + v.w*v.w;
    }
#pragma unroll
    for (int off = 16; off > 0; off >>= 1) {
        s  += __shfl_xor_sync(0xffffffffu, s,  off);
        ss += __shfl_xor_sync(0xffffffffu, ss, off);
    }
    __shared__ float red[18];
    int warp = threadIdx.x >> 5;
    if ((threadIdx.x & 31) == 0) { red[warp] = s; red[8 + warp] = ss; }
    __syncthreads();
    if (threadIdx.x == 0) {
        float S = 0.f, SS = 0.f;
        for (int w = 0; w < 8; w++) { S += red[w]; SS += red[8 + w]; }
        float mean = S * (1.0f / 65536.0f);
        float var  = SS * (1.0f / 65536.0f) - mean * mean;
        red[16] = mean;
        red[17] = rsqrtf(var + 1e-5f);
    }
    __syncthreads();
    float mean = red[16], rstd = red[17];

    float ga[16], be[16];
#pragma unroll
    for (int c = 0; c < 16; c++) {
        ga[c] = gamma[g * 16 + c] * rstd;
        be[c] = beta[g * 16 + c] - mean * ga[c];
    }

    const float* xc = x + base;
    __nv_bfloat16* hb = g_hb + (size_t)b * NTOK * CDIM + g * 16;
    for (int t = threadIdx.x; t < NTOK; t += 256) {
        unsigned w[8];
#pragma unroll
        for (int c2 = 0; c2 < 8; c2++) {
            float v0 = xc[(size_t)(2 * c2) * NTOK + t];
            float v1 = xc[(size_t)(2 * c2 + 1) * NTOK + t];
            w[c2] = packbf(v0 * ga[2 * c2] + be[2 * c2],
                           v1 * ga[2 * c2 + 1] + be[2 * c2 + 1]);
        }
        uint4* dst = (uint4*)(hb + (size_t)t * CDIM);
        dst[0] = make_uint4(w[0], w[1], w[2], w[3]);
        dst[1] = make_uint4(w[4], w[5], w[6], w[7]);
    }
}

// ---------------- bf16 QKV GEMM: Y[t][c] = sum_k A[t][k] * W[c][k] + bias ---
// Tile 128 t x 64 c, K-tile 32. 8 warps 4(t)x2(c), 32x32 each, m16n8k16.
// Both operands staged [row][k] with stride 20 words -> all frag LDS.32
// conflict-free. dst_sel: 0 g_qb / 1 g_kb (row [t][c]); 2 g_vb ([c][t] staged).
#define GSTR 20

__global__ void __launch_bounds__(256) k_gemm_qkv(int wi, const float* __restrict__ bias,
                                                  int dst_sel, float oscale)
{
    int b  = blockIdx.z;
    int t0 = blockIdx.x * 128;
    int c0 = blockIdx.y * 64;

    const __nv_bfloat16* A = g_hb + (size_t)b * NTOK * CDIM;       // [t][k]
    const __nv_bfloat16* W = g_wb + (size_t)wi * CDIM * CDIM;      // [c][k]

    __shared__ __align__(16) unsigned char smraw[33280];
    unsigned* Asw = (unsigned*)smraw;                 // [128][GSTR]
    unsigned* Wsw = (unsigned*)smraw + 128 * GSTR;    // [64][GSTR]
    float*    Cs  = (float*)smraw;                    // [128][65] epilogue

    int tid  = threadIdx.x;
    int lane = tid & 31, warp = tid >> 5;
    int r = lane >> 2, q = lane & 3;
    int wm = (warp & 3) * 32;
    int wn = (warp >> 2) * 32;

    float acc[2][4][4];
#pragma unroll
    for (int i = 0; i < 2; i++)
#pragma unroll
        for (int j = 0; j < 4; j++)
#pragma unroll
            for (int k = 0; k < 4; k++) acc[i][j][k] = 0.f;

    int arow = tid >> 1, as2 = (tid & 1) * 2;     // A: 2 uint4 per thread
    int wrow = tid >> 2, ws = tid & 3;            // W: 1 uint4 per thread

    for (int k0 = 0; k0 < CDIM; k0 += 32) {
        const uint4* asrc = (const uint4*)(A + (size_t)(t0 + arow) * CDIM + k0) + as2;
        uint4 av0 = asrc[0], av1 = asrc[1];
        *(uint4*)&Asw[arow * GSTR + as2 * 4]     = av0;
        *(uint4*)&Asw[arow * GSTR + as2 * 4 + 4] = av1;
        *(uint4*)&Wsw[wrow * GSTR + ws * 4] =
            *(const uint4*)(W + (size_t)(c0 + wrow) * CDIM + k0 + ws * 8);
        __syncthreads();

#pragma unroll
        for (int ks = 0; ks < 2; ks++) {
            int kw = ks * 8 + q;
            unsigned a[2][4], bw[4][2];
#pragma unroll
            for (int ms = 0; ms < 2; ms++) {
                int base = (wm + ms * 16 + r) * GSTR + kw;
                a[ms][0] = Asw[base];
                a[ms][1] = Asw[base + 8 * GSTR];
                a[ms][2] = Asw[base + 4];
                a[ms][3] = Asw[base + 8 * GSTR + 4];
            }
#pragma unroll
            for (int nt = 0; nt < 4; nt++) {
                int base = (wn + nt * 8 + r) * GSTR + kw;
                bw[nt][0] = Wsw[base];
                bw[nt][1] = Wsw[base + 4];
            }
#pragma unroll
            for (int ms = 0; ms < 2; ms++)
#pragma unroll
                for (int nt = 0; nt < 4; nt++)
                    mma_bf16(acc[ms][nt][0], acc[ms][nt][1], acc[ms][nt][2], acc[ms][nt][3],
                             a[ms][0], a[ms][1], a[ms][2], a[ms][3],
                             bw[nt][0], bw[nt][1]);
        }
        __syncthreads();
    }

    // bias (per channel = per C-frag column pair)
#pragma unroll
    for (int nt = 0; nt < 4; nt++) {
        float2 bi = *(const float2*)&bias[c0 + wn + nt * 8 + 2 * q];
#pragma unroll
        for (int ms = 0; ms < 2; ms++) {
            acc[ms][nt][0] += bi.x; acc[ms][nt][1] += bi.y;
            acc[ms][nt][2] += bi.x; acc[ms][nt][3] += bi.y;
        }
    }

    if (dst_sel <= 1) {
        __nv_bfloat16* Y = (dst_sel == 0 ? g_qb : g_kb);
#pragma unroll
        for (int ms = 0; ms < 2; ms++) {
            size_t row0 = (size_t)b * NTOK + t0 + wm + ms * 16 + r;
#pragma unroll
            for (int nt = 0; nt < 4; nt++) {
                int ch = c0 + wn + nt * 8 + 2 * q;
                *(__nv_bfloat162*)&Y[row0 * CDIM + ch] =
                    __floats2bfloat162_rn(acc[ms][nt][0] * oscale, acc[ms][nt][1] * oscale);
                *(__nv_bfloat162*)&Y[(row0 + 8) * CDIM + ch] =
                    __floats2bfloat162_rn(acc[ms][nt][2] * oscale, acc[ms][nt][3] * oscale);
            }
        }
    } else {
        // V: stage [t][c] then write transposed [B][C][N] bf16
#pragma unroll
        for (int ms = 0; ms < 2; ms++) {
            int rowL = wm + ms * 16 + r;
#pragma unroll
            for (int nt = 0; nt < 4; nt++) {
                int chL = wn + nt * 8 + 2 * q;
                Cs[rowL * 65 + chL]           = acc[ms][nt][0];
                Cs[rowL * 65 + chL + 1]       = acc[ms][nt][1];
                Cs[(rowL + 8) * 65 + chL]     = acc[ms][nt][2];
                Cs[(rowL + 8) * 65 + chL + 1] = acc[ms][nt][3];
            }
        }
        __syncthreads();
        for (int e = tid; e < 8192; e += 256) {
            int cL = e >> 7, nL = e & 127;
            g_vb[((size_t)b * CDIM + c0 + cL) * NTOK + t0 + nL] =
                __float2bfloat16(Cs[nL * 65 + cL]);
        }
    }
}

// ---------------- output GEMM (tf32): out = x + g_o @ Wo^T + bo --------------
#define ASTR 136
#define BSTR 72
#define CSTR 65

__global__ void __launch_bounds__(256) k_gemm_out(const float* __restrict__ bias,
                                                  const float* __restrict__ resid,
                                                  float* __restrict__ outp)
{
    int b  = blockIdx.z;
    int t0 = blockIdx.x * 128;
    int c0 = blockIdx.y * 64;

    const float* A  = g_o + (size_t)b * CDIM * NTOK;   // [k][t]
    const float* Wt = g_wt;                            // [k][c]

    __shared__ float sm[128 * CSTR];
    float* As = sm;
    float* Bs = sm + 32 * ASTR;

    int tid  = threadIdx.x;
    int lane = tid & 31, warp = tid >> 5;
    int r = lane >> 2, q = lane & 3;
    int wm = (warp & 3) * 32;
    int wn = (warp >> 2) * 32;

    float acc[2][4][4];
#pragma unroll
    for (int i = 0; i < 2; i++)
#pragma unroll
        for (int j = 0; j < 4; j++)
#pragma unroll
            for (int k = 0; k < 4; k++) acc[i][j][k] = 0.f;

    int arow = tid >> 3, acl = tid & 7;
    int brow0 = tid >> 4, bcl = tid & 15;

    for (int k0 = 0; k0 < CDIM; k0 += 32) {
#pragma unroll
        for (int it = 0; it < 4; it++) {
            int col = 4 * (acl + 8 * it);
            float4 v = *(const float4*)&A[(size_t)(k0 + arow) * NTOK + t0 + col];
            As[arow * ASTR + col + 0] = tf32r(v.x);
            As[arow * ASTR + col + 1] = tf32r(v.y);
            As[arow * ASTR + col + 2] = tf32r(v.z);
            As[arow * ASTR + col + 3] = tf32r(v.w);
        }
#pragma unroll
        for (int it = 0; it < 2; it++) {
            int row = brow0 + it * 16;
            int col = 4 * bcl;
            float4 v = *(const float4*)&Wt[(size_t)(k0 + row) * CDIM + c0 + col];
            Bs[row * BSTR + col + 0] = tf32r(v.x);
            Bs[row * BSTR + col + 1] = tf32r(v.y);
            Bs[row * BSTR + col + 2] = tf32r(v.z);
            Bs[row * BSTR + col + 3] = tf32r(v.w);
        }
        __syncthreads();

#pragma unroll
        for (int ks = 0; ks < 4; ks++) {
            int k8 = ks * 8;
            float a[2][4], bb[4][2];
#pragma unroll
            for (int ms = 0; ms < 2; ms++) {
                int ml = wm + ms * 16;
                a[ms][0] = As[(k8 + q) * ASTR + ml + r];
                a[ms][1] = As[(k8 + q) * ASTR + ml + r + 8];
                a[ms][2] = As[(k8 + q + 4) * ASTR + ml + r];
                a[ms][3] = As[(k8 + q + 4) * ASTR + ml + r + 8];
            }
#pragma unroll
            for (int ns = 0; ns < 4; ns++) {
                int nl = wn + ns * 8;
                bb[ns][0] = Bs[(k8 + q) * BSTR + nl + r];
                bb[ns][1] = Bs[(k8 + q + 4) * BSTR + nl + r];
            }
#pragma unroll
            for (int ms = 0; ms < 2; ms++)
#pragma unroll
                for (int ns = 0; ns < 4; ns++)
                    mma_tf32(acc[ms][ns][0], acc[ms][ns][1], acc[ms][ns][2], acc[ms][ns][3],
                             a[ms][0], a[ms][1], a[ms][2], a[ms][3],
                             bb[ns][0], bb[ns][1]);
        }
        __syncthreads();
    }

#pragma unroll
    for (int ns = 0; ns < 4; ns++) {
        float2 bi = *(const float2*)&bias[c0 + wn + ns * 8 + 2 * q];
#pragma unroll
        for (int ms = 0; ms < 2; ms++) {
            acc[ms][ns][0] += bi.x; acc[ms][ns][1] += bi.y;
            acc[ms][ns][2] += bi.x; acc[ms][ns][3] += bi.y;
        }
    }

    float* Cs = sm;
#pragma unroll
    for (int ms = 0; ms < 2; ms++) {
        int rowL = wm + ms * 16 + r;
#pragma unroll
        for (int ns = 0; ns < 4; ns++) {
            int chL = wn + ns * 8 + 2 * q;
            Cs[rowL * CSTR + chL]           = acc[ms][ns][0];
            Cs[rowL * CSTR + chL + 1]       = acc[ms][ns][1];
            Cs[(rowL + 8) * CSTR + chL]     = acc[ms][ns][2];
            Cs[(rowL + 8) * CSTR + chL + 1] = acc[ms][ns][3];
        }
    }
    __syncthreads();
    for (int e = tid; e < 8192; e += 256) {
        int cL = e >> 7, nL = e & 127;
        size_t idx = ((size_t)b * CDIM + c0 + cL) * NTOK + t0 + nL;
        outp[idx] = Cs[nL * CSTR + cL] + resid[idx];
    }
}

// ---------------- attention: flash-style, bf16 m16n8k16, cp.async pipe -----
#define KW 36   // row stride in 32-bit words (72 bf16)
#define BUFB 18432

__global__ void __launch_bounds__(256) k_attn()
{
    __shared__ __align__(16) unsigned char smraw[2 * BUFB];   // 36864 B
    unsigned* Qw = (unsigned*)smraw;                 // [128][KW] (pre-loop only)
    float*    Es = (float*)smraw;                    // [64][71]  (epilogue only)

    int tid  = threadIdx.x;
    int lane = tid & 31, warp = tid >> 5;
    int r = lane >> 2, q = lane & 3;
    int n0 = blockIdx.x * 128;
    int h  = blockIdx.y;
    int b  = blockIdx.z;

    // ---- stage Q (already bf16, pre-scaled by log2e/8 in GEMM) ----
    {
        const __nv_bfloat16* Qg = g_qb + ((size_t)b * NTOK + n0) * CDIM + h * HD;
        int row = tid >> 1, s = tid & 1;
#pragma unroll
        for (int it = 0; it < 4; it++) {
            int col = 8 * (4 * s + it);
            uint4 v = *(const uint4*)&Qg[(size_t)row * CDIM + col];
            *(uint4*)&Qw[row * KW + (col >> 1)] = v;
        }
    }
    __syncthreads();

    unsigned aq[4][4];
    {
        int rb = warp * 16 + r;
#pragma unroll
        for (int kt = 0; kt < 4; kt++) {
            int base = kt * 8 + q;
            aq[kt][0] = Qw[rb * KW + base];
            aq[kt][1] = Qw[(rb + 8) * KW + base];
            aq[kt][2] = Qw[rb * KW + base + 4];
            aq[kt][3] = Qw[(rb + 8) * KW + base + 4];
        }
    }
    __syncthreads();

    float o[8][4];
#pragma unroll
    for (int i = 0; i < 8; i++)
#pragma unroll
        for (int j = 0; j < 4; j++) o[i][j] = 0.f;
    float m0 = -1e30f, m1 = -1e30f, l0 = 0.f, l1 = 0.f;

    const __nv_bfloat16* Kg = g_kb + (size_t)b * NTOK * CDIM + h * HD;
    const __nv_bfloat16* Vg = g_vb + ((size_t)b * CDIM + h * HD) * NTOK;

    int srow = tid >> 2, sseg = tid & 3;
    unsigned sbase = (unsigned)__cvta_generic_to_shared(smraw);
    unsigned kdoff = (srow * KW + sseg * 8) * 4;     // byte offset in buffer

    // prefetch tiles 0 and 1
#pragma unroll
    for (int p = 0; p < 2; p++) {
        unsigned kd = sbase + p * BUFB + kdoff;
        const __nv_bfloat16* ksrc = Kg + (size_t)srow * CDIM + p * 64 + 0;
        // K rows indexed by key j: key = p*64 + srow
        ksrc = Kg + (size_t)(p * 64 + srow) * CDIM + sseg * 16;
        const __nv_bfloat16* vsrc = Vg + (size_t)srow * NTOK + p * 64 + sseg * 16;
        cpa16(kd, ksrc); cpa16(kd + 16, ksrc + 8);
        cpa16(kd + 9216, vsrc); cpa16(kd + 9216 + 16, vsrc + 8);
        CP_COMMIT();
    }

    for (int it = 0; it < NTOK / 64; it++) {
        CP_WAIT1();
        __syncthreads();
        int buf = it & 1;
        unsigned* Kw = (unsigned*)(smraw + buf * BUFB);
        unsigned* Vw = (unsigned*)(smraw + buf * BUFB + 9216);

        // ---- S = Q * K^T (log2 space) ----
        float s[8][4];
#pragma unroll
        for (int i = 0; i < 8; i++)
#pragma unroll
            for (int j = 0; j < 4; j++) s[i][j] = 0.f;

#pragma unroll
        for (int kt = 0; kt < 4; kt++) {
#pragma unroll
            for (int nt = 0; nt < 8; nt++) {
                unsigned b0 = Kw[(nt * 8 + r) * KW + kt * 8 + q];
                unsigned b1 = Kw[(nt * 8 + r) * KW + kt * 8 + q + 4];
                mma_bf16(s[nt][0], s[nt][1], s[nt][2], s[nt][3],
                         aq[kt][0], aq[kt][1], aq[kt][2], aq[kt][3], b0, b1);
            }
        }

        // ---- online softmax (base-2) ----
        float mx0 = -1e30f, mx1 = -1e30f;
#pragma unroll
        for (int nt = 0; nt < 8; nt++) {
            mx0 = fmaxf(mx0, fmaxf(s[nt][0], s[nt][1]));
            mx1 = fmaxf(mx1, fmaxf(s[nt][2], s[nt][3]));
        }
        mx0 = fmaxf(mx0, __shfl_xor_sync(0xffffffffu, mx0, 1));
        mx0 = fmaxf(mx0, __shfl_xor_sync(0xffffffffu, mx0, 2));
        mx1 = fmaxf(mx1, __shfl_xor_sync(0xffffffffu, mx1, 1));
        mx1 = fmaxf(mx1, __shfl_xor_sync(0xffffffffu, mx1, 2));

        float mn0 = fmaxf(m0, mx0), mn1 = fmaxf(m1, mx1);
        float al0 = exp2f(m0 - mn0), al1 = exp2f(m1 - mn1);
        float sum0 = 0.f, sum1 = 0.f;
#pragma unroll
        for (int nt = 0; nt < 8; nt++) {
            s[nt][0] = exp2f(s[nt][0] - mn0);
            s[nt][1] = exp2f(s[nt][1] - mn0);
            s[nt][2] = exp2f(s[nt][2] - mn1);
            s[nt][3] = exp2f(s[nt][3] - mn1);
            sum0 += s[nt][0] + s[nt][1];
            sum1 += s[nt][2] + s[nt][3];
        }
        sum0 += __shfl_xor_sync(0xffffffffu, sum0, 1);
        sum0 += __shfl_xor_sync(0xffffffffu, sum0, 2);
        sum1 += __shfl_xor_sync(0xffffffffu, sum1, 1);
        sum1 += __shfl_xor_sync(0xffffffffu, sum1, 2);

        l0 = l0 * al0 + sum0;  m0 = mn0;
        l1 = l1 * al1 + sum1;  m1 = mn1;
#pragma unroll
        for (int ct = 0; ct < 8; ct++) {
            o[ct][0] *= al0; o[ct][1] *= al0;
            o[ct][2] *= al1; o[ct][3] *= al1;
        }

        // ---- O += P * V ----
#pragma unroll
        for (int kt = 0; kt < 4; kt++) {
            unsigned a0 = packbf(s[2*kt][0],     s[2*kt][1]);
            unsigned a1 = packbf(s[2*kt][2],     s[2*kt][3]);
            unsigned a2 = packbf(s[2*kt + 1][0], s[2*kt + 1][1]);
            unsigned a3 = packbf(s[2*kt + 1][2], s[2*kt + 1][3]);
#pragma unroll
            for (int ct = 0; ct < 8; ct++) {
                unsigned b0 = Vw[(ct * 8 + r) * KW + kt * 8 + q];
                unsigned b1 = Vw[(ct * 8 + r) * KW + kt * 8 + q + 4];
                mma_bf16(o[ct][0], o[ct][1], o[ct][2], o[ct][3],
                         a0, a1, a2, a3, b0, b1);
            }
        }
        __syncthreads();

        // ---- prefetch tile it+2 into this (now dead) buffer ----
        int jn = (it + 2) * 64;
        if (jn < NTOK) {
            unsigned kd = sbase + buf * BUFB + kdoff;
            const __nv_bfloat16* ksrc = Kg + (size_t)(jn + srow) * CDIM + sseg * 16;
            const __nv_bfloat16* vsrc = Vg + (size_t)srow * NTOK + jn + sseg * 16;
            cpa16(kd, ksrc); cpa16(kd + 16, ksrc + 8);
            cpa16(kd + 9216, vsrc); cpa16(kd + 9216 + 16, vsrc + 8);
        }
        CP_COMMIT();
    }

    // ---- epilogue: normalize, two-phase smem transpose, write [B][C][N] ----
    float il0 = 1.0f / l0, il1 = 1.0f / l1;
#pragma unroll
    for (int ph = 0; ph < 2; ph++) {
        if ((warp >> 2) == ph) {
            int rowL = (warp & 3) * 16 + r;
#pragma unroll
            for (int ct = 0; ct < 8; ct++) {
                int cc = ct * 8 + 2 * q;
                Es[rowL * 71 + cc]           = o[ct][0] * il0;
                Es[rowL * 71 + cc + 1]       = o[ct][1] * il0;
                Es[(rowL + 8) * 71 + cc]     = o[ct][2] * il1;
                Es[(rowL + 8) * 71 + cc + 1] = o[ct][3] * il1;
            }
        }
        __syncthreads();
        for (int e = tid; e < 4096; e += 256) {
            int c = e >> 6, n = e & 63;
            g_o[((size_t)b * CDIM + h * HD + c) * NTOK + n0 + ph * 64 + n] = Es[n * 71 + c];
        }
        __syncthreads();
    }
}

// ---------------- launch ----------------------------------------------------
extern "C" void kernel_launch(void* const* d_in, const int* in_sizes, int n_in,
                              void* d_out, int out_size)
{
    const float* x     = (const float*)d_in[0];
    const float* gamma = (const float*)d_in[1];
    const float* beta  = (const float*)d_in[2];
    const float* Wq    = (const float*)d_in[3];
    const float* bq    = (const float*)d_in[4];
    const float* Wk    = (const float*)d_in[5];
    const float* bk    = (const float*)d_in[6];
    const float* Wv    = (const float*)d_in[7];
    const float* bv    = (const float*)d_in[8];
    const float* Wo    = (const float*)d_in[9];
    const float* bo    = (const float*)d_in[10];
    float* out = (float*)d_out;

    const float SCL = 0.125f * 1.4426950408889634f;   // (1/sqrt(hd)) * log2(e)

    k_wconv<<<dim3(512, 3), 256>>>(Wq, Wk, Wv);
    k_transpose<<<dim3(CDIM/32, CDIM/32), dim3(32, 8)>>>(Wo);
    k_groupnorm<<<BATCH * GROUPS, 256>>>(x, gamma, beta);

    dim3 gg(NTOK / 128, CDIM / 64, BATCH);
    k_gemm_qkv<<<gg, 256>>>(0, bq, 0, SCL);    // Q -> g_qb (pre-scaled)
    k_gemm_qkv<<<gg, 256>>>(1, bk, 1, 1.0f);   // K -> g_kb
    k_gemm_qkv<<<gg, 256>>>(2, bv, 2, 1.0f);   // V -> g_vb (transposed)

    k_attn<<<dim3(NTOK / 128, HEADS, BATCH), 256>>>();

    k_gemm_out<<<gg, 256>>>(bo, x, out);       // out = x + g_o @ Wo^T + bo
}

// round 6
// speedup vs baseline: 4.9742x; 1.0106x over previous
#include <cuda_runtime.h>
#include <cuda_bf16.h>
#include <math.h>

#define BATCH  2
#define CDIM   512
#define NTOK   4096
#define HEADS  8
#define HD     64
#define GROUPS 32

// ---------------- scratch (static device globals; no allocations) ----------
__device__ __nv_bfloat16 g_hb[(size_t)BATCH*NTOK*CDIM];   // GN out, [B][N][C]
__device__ __nv_bfloat16 g_qb[(size_t)BATCH*NTOK*CDIM];   // Q (pre-scaled), [B][N][C]
__device__ __nv_bfloat16 g_kb[(size_t)BATCH*NTOK*CDIM];   // K, [B][N][C]
__device__ __nv_bfloat16 g_vb[(size_t)BATCH*CDIM*NTOK];   // V, [B][C][N]
__device__ float g_o [(size_t)BATCH*CDIM*NTOK];           // attn out, [B][C][N]
__device__ float g_wt[(size_t)CDIM*CDIM];                 // Wo^T fp32 [k][m]
__device__ __nv_bfloat16 g_wb[3*(size_t)CDIM*CDIM];       // Wq,Wk,Wv bf16 [c][k]

// ---------------- helpers ---------------------------------------------------
__device__ __forceinline__ float tf32r(float x) {
    asm("cvt.rna.tf32.f32 %0, %0;" : "+f"(x));
    return x;
}

__device__ __forceinline__ void mma_tf32(float& d0, float& d1, float& d2, float& d3,
                                         float a0, float a1, float a2, float a3,
                                         float b0, float b1)
{
    asm volatile("mma.sync.aligned.m16n8k8.row.col.f32.tf32.tf32.f32 "
                 "{%0,%1,%2,%3},{%4,%5,%6,%7},{%8,%9},{%0,%1,%2,%3};"
                 : "+f"(d0), "+f"(d1), "+f"(d2), "+f"(d3)
                 : "f"(a0), "f"(a1), "f"(a2), "f"(a3), "f"(b0), "f"(b1));
}

__device__ __forceinline__ void mma_bf16(float& d0, float& d1, float& d2, float& d3,
                                         unsigned a0, unsigned a1, unsigned a2, unsigned a3,
                                         unsigned b0, unsigned b1)
{
    asm volatile("mma.sync.aligned.m16n8k16.row.col.f32.bf16.bf16.f32 "
                 "{%0,%1,%2,%3},{%4,%5,%6,%7},{%8,%9},{%0,%1,%2,%3};"
                 : "+f"(d0), "+f"(d1), "+f"(d2), "+f"(d3)
                 : "r"(a0), "r"(a1), "r"(a2), "r"(a3), "r"(b0), "r"(b1));
}

__device__ __forceinline__ unsigned packbf(float lo, float hi) {
    __nv_bfloat162 p = __floats2bfloat162_rn(lo, hi);
    return *(unsigned*)&p;
}

__device__ __forceinline__ void cpa16(unsigned dst, const void* src) {
    asm volatile("cp.async.ca.shared.global [%0], [%1], 16;" :: "r"(dst), "l"(src));
}
#define CP_COMMIT() asm volatile("cp.async.commit_group;")
#define CP_WAIT1()  asm volatile("cp.async.wait_group 1;")
#define CP_WAIT0()  asm volatile("cp.async.wait_group 0;")

// ---------------- weight prep ------------------------------------------------
__global__ void k_wconv(const float* __restrict__ W0, const float* __restrict__ W1,
                        const float* __restrict__ W2)
{
    const float* srcs[3] = {W0, W1, W2};
    const float* W = srcs[blockIdx.y];
    __nv_bfloat16* dst = g_wb + (size_t)blockIdx.y * CDIM * CDIM;
    size_t i2 = ((size_t)blockIdx.x * 256 + threadIdx.x) * 2;
    float2 v = *(const float2*)&W[i2];
    *(__nv_bfloat162*)&dst[i2] = __floats2bfloat162_rn(v.x, v.y);
}

__global__ void k_transpose(const float* __restrict__ W)
{
    __shared__ float tile[32][33];
    int x = blockIdx.x * 32 + threadIdx.x;
    int y = blockIdx.y * 32 + threadIdx.y;
#pragma unroll
    for (int i = 0; i < 32; i += 8)
        tile[threadIdx.y + i][threadIdx.x] = W[(size_t)(y + i) * CDIM + x];
    __syncthreads();
    int x2 = blockIdx.y * 32 + threadIdx.x;
    int y2 = blockIdx.x * 32 + threadIdx.y;
#pragma unroll
    for (int i = 0; i < 32; i += 8)
        g_wt[(size_t)(y2 + i) * CDIM + x2] = tile[threadIdx.x][threadIdx.y + i];
}

// ---------------- GroupNorm: one block per (b, g); writes bf16 [B][N][C] ----
__global__ void k_groupnorm(const float* __restrict__ x,
                            const float* __restrict__ gamma,
                            const float* __restrict__ beta)
{
    int b = blockIdx.x >> 5;
    int g = blockIdx.x & 31;
    size_t base = ((size_t)b * CDIM + g * 16) * NTOK;
    const float4* xp = (const float4*)(x + base);

    float s = 0.f, ss = 0.f;
    for (int i = threadIdx.x; i < 16384; i += 256) {
        float4 v = xp[i];
        s  += v.x + v.y + v.z + v.w;
        ss += v.x*v.x + v.y*v.y + v.z*v.z + v.w*v.w;
    }
#pragma unroll
    for (int off = 16; off > 0; off >>= 1) {
        s  += __shfl_xor_sync(0xffffffffu, s,  off);
        ss += __shfl_xor_sync(0xffffffffu, ss, off);
    }
    __shared__ float red[18];
    int warp = threadIdx.x >> 5;
    if ((threadIdx.x & 31) == 0) { red[warp] = s; red[8 + warp] = ss; }
    __syncthreads();
    if (threadIdx.x == 0) {
        float S = 0.f, SS = 0.f;
        for (int w = 0; w < 8; w++) { S += red[w]; SS += red[8 + w]; }
        float mean = S * (1.0f / 65536.0f);
        float var  = SS * (1.0f / 65536.0f) - mean * mean;
        red[16] = mean;
        red[17] = rsqrtf(var + 1e-5f);
    }
    __syncthreads();
    float mean = red[16], rstd = red[17];

    float ga[16], be[16];
#pragma unroll
    for (int c = 0; c < 16; c++) {
        ga[c] = gamma[g * 16 + c] * rstd;
        be[c] = beta[g * 16 + c] - mean * ga[c];
    }

    const float* xc = x + base;
    __nv_bfloat16* hb = g_hb + (size_t)b * NTOK * CDIM + g * 16;
    for (int t = threadIdx.x; t < NTOK; t += 256) {
        unsigned w[8];
#pragma unroll
        for (int c2 = 0; c2 < 8; c2++) {
            float v0 = xc[(size_t)(2 * c2) * NTOK + t];
            float v1 = xc[(size_t)(2 * c2 + 1) * NTOK + t];
            w[c2] = packbf(v0 * ga[2 * c2] + be[2 * c2],
                           v1 * ga[2 * c2 + 1] + be[2 * c2 + 1]);
        }
        uint4* dst = (uint4*)(hb + (size_t)t * CDIM);
        dst[0] = make_uint4(w[0], w[1], w[2], w[3]);
        dst[1] = make_uint4(w[4], w[5], w[6], w[7]);
    }
}

// ---------------- bf16 QKV GEMM, cp.async double-buffered -------------------
// Tile 128 t x 64 c, K-tile 32. Buffers: A [128][20w] + W [64][20w] = 15360 B.
#define GSTR 20
#define QBUF 15360

__global__ void __launch_bounds__(256) k_gemm_qkv(int wi, const float* __restrict__ bias,
                                                  int dst_sel, float oscale)
{
    int b  = blockIdx.z;
    int t0 = blockIdx.x * 128;
    int c0 = blockIdx.y * 64;

    const __nv_bfloat16* A = g_hb + (size_t)b * NTOK * CDIM;       // [t][k]
    const __nv_bfloat16* W = g_wb + (size_t)wi * CDIM * CDIM;      // [c][k]

    __shared__ __align__(16) unsigned char smraw[33280];
    float* Cs = (float*)smraw;                        // [128][65] epilogue

    int tid  = threadIdx.x;
    int lane = tid & 31, warp = tid >> 5;
    int r = lane >> 2, q = lane & 3;
    int wm = (warp & 3) * 32;
    int wn = (warp >> 2) * 32;

    float acc[2][4][4];
#pragma unroll
    for (int i = 0; i < 2; i++)
#pragma unroll
        for (int j = 0; j < 4; j++)
#pragma unroll
            for (int k = 0; k < 4; k++) acc[i][j][k] = 0.f;

    unsigned sbase = (unsigned)__cvta_generic_to_shared(smraw);
    int arow = tid >> 1, ac = (tid & 1) * 2;    // A: rows 0..127, 2 chunks each
    int wrow = tid >> 2, wc = tid & 3;          // W: rows 0..63,  1 chunk each

    // prefetch k-tiles 0 and 1
#pragma unroll
    for (int p = 0; p < 2; p++) {
        int k0 = p * 32;
        unsigned ad = sbase + p * QBUF + arow * 80 + ac * 16;
        const __nv_bfloat16* as = A + (size_t)(t0 + arow) * CDIM + k0 + ac * 8;
        cpa16(ad, as); cpa16(ad + 16, as + 8);
        cpa16(sbase + p * QBUF + 10240 + wrow * 80 + wc * 16,
              W + (size_t)(c0 + wrow) * CDIM + k0 + wc * 8);
        CP_COMMIT();
    }

    for (int kit = 0; kit < CDIM / 32; kit++) {
        CP_WAIT1();
        __syncthreads();
        unsigned* Asw = (unsigned*)(smraw + (kit & 1) * QBUF);
        unsigned* Wsw = Asw + 2560;

#pragma unroll
        for (int ks = 0; ks < 2; ks++) {
            int kw = ks * 8 + q;
            unsigned a[2][4], bw[4][2];
#pragma unroll
            for (int ms = 0; ms < 2; ms++) {
                int base = (wm + ms * 16 + r) * GSTR + kw;
                a[ms][0] = Asw[base];
                a[ms][1] = Asw[base + 8 * GSTR];
                a[ms][2] = Asw[base + 4];
                a[ms][3] = Asw[base + 8 * GSTR + 4];
            }
#pragma unroll
            for (int nt = 0; nt < 4; nt++) {
                int base = (wn + nt * 8 + r) * GSTR + kw;
                bw[nt][0] = Wsw[base];
                bw[nt][1] = Wsw[base + 4];
            }
#pragma unroll
            for (int ms = 0; ms < 2; ms++)
#pragma unroll
                for (int nt = 0; nt < 4; nt++)
                    mma_bf16(acc[ms][nt][0], acc[ms][nt][1], acc[ms][nt][2], acc[ms][nt][3],
                             a[ms][0], a[ms][1], a[ms][2], a[ms][3],
                             bw[nt][0], bw[nt][1]);
        }
        __syncthreads();

        int k2 = (kit + 2) * 32;
        if (k2 < CDIM) {
            int p = kit & 1;
            unsigned ad = sbase + p * QBUF + arow * 80 + ac * 16;
            const __nv_bfloat16* as = A + (size_t)(t0 + arow) * CDIM + k2 + ac * 8;
            cpa16(ad, as); cpa16(ad + 16, as + 8);
            cpa16(sbase + p * QBUF + 10240 + wrow * 80 + wc * 16,
                  W + (size_t)(c0 + wrow) * CDIM + k2 + wc * 8);
        }
        CP_COMMIT();
    }

    // bias
#pragma unroll
    for (int nt = 0; nt < 4; nt++) {
        float2 bi = *(const float2*)&bias[c0 + wn + nt * 8 + 2 * q];
#pragma unroll
        for (int ms = 0; ms < 2; ms++) {
            acc[ms][nt][0] += bi.x; acc[ms][nt][1] += bi.y;
            acc[ms][nt][2] += bi.x; acc[ms][nt][3] += bi.y;
        }
    }

    if (dst_sel <= 1) {
        __nv_bfloat16* Y = (dst_sel == 0 ? g_qb : g_kb);
#pragma unroll
        for (int ms = 0; ms < 2; ms++) {
            size_t row0 = (size_t)b * NTOK + t0 + wm + ms * 16 + r;
#pragma unroll
            for (int nt = 0; nt < 4; nt++) {
                int ch = c0 + wn + nt * 8 + 2 * q;
                *(__nv_bfloat162*)&Y[row0 * CDIM + ch] =
                    __floats2bfloat162_rn(acc[ms][nt][0] * oscale, acc[ms][nt][1] * oscale);
                *(__nv_bfloat162*)&Y[(row0 + 8) * CDIM + ch] =
                    __floats2bfloat162_rn(acc[ms][nt][2] * oscale, acc[ms][nt][3] * oscale);
            }
        }
    } else {
        CP_WAIT0();
        __syncthreads();
#pragma unroll
        for (int ms = 0; ms < 2; ms++) {
            int rowL = wm + ms * 16 + r;
#pragma unroll
            for (int nt = 0; nt < 4; nt++) {
                int chL = wn + nt * 8 + 2 * q;
                Cs[rowL * 65 + chL]           = acc[ms][nt][0];
                Cs[rowL * 65 + chL + 1]       = acc[ms][nt][1];
                Cs[(rowL + 8) * 65 + chL]     = acc[ms][nt][2];
                Cs[(rowL + 8) * 65 + chL + 1] = acc[ms][nt][3];
            }
        }
        __syncthreads();
        for (int e = tid; e < 8192; e += 256) {
            int cL = e >> 7, nL = e & 127;
            g_vb[((size_t)b * CDIM + c0 + cL) * NTOK + t0 + nL] =
                __float2bfloat16(Cs[nL * 65 + cL]);
        }
    }
}

// ---------------- output GEMM (tf32): out = x + g_o @ Wo^T + bo --------------
#define ASTR 136
#define BSTR 72
#define CSTR 65

__global__ void __launch_bounds__(256) k_gemm_out(const float* __restrict__ bias,
                                                  const float* __restrict__ resid,
                                                  float* __restrict__ outp)
{
    int b  = blockIdx.z;
    int t0 = blockIdx.x * 128;
    int c0 = blockIdx.y * 64;

    const float* A  = g_o + (size_t)b * CDIM * NTOK;   // [k][t]
    const float* Wt = g_wt;                            // [k][c]

    __shared__ float sm[128 * CSTR];
    float* As = sm;
    float* Bs = sm + 32 * ASTR;

    int tid  = threadIdx.x;
    int lane = tid & 31, warp = tid >> 5;
    int r = lane >> 2, q = lane & 3;
    int wm = (warp & 3) * 32;
    int wn = (warp >> 2) * 32;

    float acc[2][4][4];
#pragma unroll
    for (int i = 0; i < 2; i++)
#pragma unroll
        for (int j = 0; j < 4; j++)
#pragma unroll
            for (int k = 0; k < 4; k++) acc[i][j][k] = 0.f;

    int arow = tid >> 3, acl = tid & 7;
    int brow0 = tid >> 4, bcl = tid & 15;

    for (int k0 = 0; k0 < CDIM; k0 += 32) {
#pragma unroll
        for (int it = 0; it < 4; it++) {
            int col = 4 * (acl + 8 * it);
            float4 v = *(const float4*)&A[(size_t)(k0 + arow) * NTOK + t0 + col];
            As[arow * ASTR + col + 0] = tf32r(v.x);
            As[arow * ASTR + col + 1] = tf32r(v.y);
            As[arow * ASTR + col + 2] = tf32r(v.z);
            As[arow * ASTR + col + 3] = tf32r(v.w);
        }
#pragma unroll
        for (int it = 0; it < 2; it++) {
            int row = brow0 + it * 16;
            int col = 4 * bcl;
            float4 v = *(const float4*)&Wt[(size_t)(k0 + row) * CDIM + c0 + col];
            Bs[row * BSTR + col + 0] = tf32r(v.x);
            Bs[row * BSTR + col + 1] = tf32r(v.y);
            Bs[row * BSTR + col + 2] = tf32r(v.z);
            Bs[row * BSTR + col + 3] = tf32r(v.w);
        }
        __syncthreads();

#pragma unroll
        for (int ks = 0; ks < 4; ks++) {
            int k8 = ks * 8;
            float a[2][4], bb[4][2];
#pragma unroll
            for (int ms = 0; ms < 2; ms++) {
                int ml = wm + ms * 16;
                a[ms][0] = As[(k8 + q) * ASTR + ml + r];
                a[ms][1] = As[(k8 + q) * ASTR + ml + r + 8];
                a[ms][2] = As[(k8 + q + 4) * ASTR + ml + r];
                a[ms][3] = As[(k8 + q + 4) * ASTR + ml + r + 8];
            }
#pragma unroll
            for (int ns = 0; ns < 4; ns++) {
                int nl = wn + ns * 8;
                bb[ns][0] = Bs[(k8 + q) * BSTR + nl + r];
                bb[ns][1] = Bs[(k8 + q + 4) * BSTR + nl + r];
            }
#pragma unroll
            for (int ms = 0; ms < 2; ms++)
#pragma unroll
                for (int ns = 0; ns < 4; ns++)
                    mma_tf32(acc[ms][ns][0], acc[ms][ns][1], acc[ms][ns][2], acc[ms][ns][3],
                             a[ms][0], a[ms][1], a[ms][2], a[ms][3],
                             bb[ns][0], bb[ns][1]);
        }
        __syncthreads();
    }

#pragma unroll
    for (int ns = 0; ns < 4; ns++) {
        float2 bi = *(const float2*)&bias[c0 + wn + ns * 8 + 2 * q];
#pragma unroll
        for (int ms = 0; ms < 2; ms++) {
            acc[ms][ns][0] += bi.x; acc[ms][ns][1] += bi.y;
            acc[ms][ns][2] += bi.x; acc[ms][ns][3] += bi.y;
        }
    }

    float* Cs = sm;
#pragma unroll
    for (int ms = 0; ms < 2; ms++) {
        int rowL = wm + ms * 16 + r;
#pragma unroll
        for (int ns = 0; ns < 4; ns++) {
            int chL = wn + ns * 8 + 2 * q;
            Cs[rowL * CSTR + chL]           = acc[ms][ns][0];
            Cs[rowL * CSTR + chL + 1]       = acc[ms][ns][1];
            Cs[(rowL + 8) * CSTR + chL]     = acc[ms][ns][2];
            Cs[(rowL + 8) * CSTR + chL + 1] = acc[ms][ns][3];
        }
    }
    __syncthreads();
    for (int e = tid; e < 8192; e += 256) {
        int cL = e >> 7, nL = e & 127;
        size_t idx = ((size_t)b * CDIM + c0 + cL) * NTOK + t0 + nL;
        outp[idx] = Cs[nL * CSTR + cL] + resid[idx];
    }
}

// ---------------- attention: 4 warps x 32 rows, bf16 mma, cp.async ----------
// Each warp owns 32 query rows (2 m16 frags); each K/V B-frag load feeds 2 mmas.
#define KW 36      // row stride in 32-bit words (72 bf16)
#define BUFB 18432

__global__ void __launch_bounds__(128) k_attn()
{
    __shared__ __align__(16) unsigned char smraw[2 * BUFB];   // 36864 B
    unsigned* Qw = (unsigned*)smraw;                 // [128][KW] (pre-loop only)
    float*    Es = (float*)smraw;                    // [64][71]  (epilogue only)

    int tid  = threadIdx.x;
    int lane = tid & 31, warp = tid >> 5;
    int r = lane >> 2, q = lane & 3;
    int n0 = blockIdx.x * 128;
    int h  = blockIdx.y;
    int b  = blockIdx.z;

    // ---- stage Q (bf16, pre-scaled by log2e/8 in GEMM) ----
    {
        const __nv_bfloat16* Qg = g_qb + ((size_t)b * NTOK + n0) * CDIM + h * HD;
#pragma unroll
        for (int it = 0; it < 8; it++) {
            uint4 v = *(const uint4*)&Qg[(size_t)tid * CDIM + it * 8];
            *(uint4*)&Qw[tid * KW + it * 4] = v;
        }
    }
    __syncthreads();

    unsigned aq[2][4][4];
#pragma unroll
    for (int mf = 0; mf < 2; mf++) {
        int rb = warp * 32 + mf * 16 + r;
#pragma unroll
        for (int kt = 0; kt < 4; kt++) {
            int base = kt * 8 + q;
            aq[mf][kt][0] = Qw[rb * KW + base];
            aq[mf][kt][1] = Qw[(rb + 8) * KW + base];
            aq[mf][kt][2] = Qw[rb * KW + base + 4];
            aq[mf][kt][3] = Qw[(rb + 8) * KW + base + 4];
        }
    }
    __syncthreads();

    float o[2][8][4];
#pragma unroll
    for (int mf = 0; mf < 2; mf++)
#pragma unroll
        for (int i = 0; i < 8; i++)
#pragma unroll
            for (int j = 0; j < 4; j++) o[mf][i][j] = 0.f;
    float m_i[2][2], l_i[2][2];
#pragma unroll
    for (int mf = 0; mf < 2; mf++) { m_i[mf][0] = m_i[mf][1] = -1e30f;
                                     l_i[mf][0] = l_i[mf][1] = 0.f; }

    const __nv_bfloat16* Kg = g_kb + (size_t)b * NTOK * CDIM + h * HD;
    const __nv_bfloat16* Vg = g_vb + ((size_t)b * CDIM + h * HD) * NTOK;

    int srow = tid >> 1, sh = tid & 1;           // 64 rows x 2 halves
    unsigned sbase = (unsigned)__cvta_generic_to_shared(smraw);
    unsigned doff = srow * 144 + sh * 64;        // byte offset inside buffer

    // prefetch tiles 0 and 1
#pragma unroll
    for (int p = 0; p < 2; p++) {
        unsigned kd = sbase + p * BUFB + doff;
        const __nv_bfloat16* ksrc = Kg + (size_t)(p * 64 + srow) * CDIM + sh * 32;
        const __nv_bfloat16* vsrc = Vg + (size_t)srow * NTOK + p * 64 + sh * 32;
#pragma unroll
        for (int j = 0; j < 4; j++) {
            cpa16(kd + j * 16, ksrc + j * 8);
            cpa16(kd + 9216 + j * 16, vsrc + j * 8);
        }
        CP_COMMIT();
    }

    for (int it = 0; it < NTOK / 64; it++) {
        CP_WAIT1();
        __syncthreads();
        int buf = it & 1;
        unsigned* Kw = (unsigned*)(smraw + buf * BUFB);
        unsigned* Vw = (unsigned*)(smraw + buf * BUFB + 9216);

        // ---- S = Q * K^T : each B-frag load feeds both M-frags ----
        float s[2][8][4];
#pragma unroll
        for (int mf = 0; mf < 2; mf++)
#pragma unroll
            for (int i = 0; i < 8; i++)
#pragma unroll
                for (int j = 0; j < 4; j++) s[mf][i][j] = 0.f;

#pragma unroll
        for (int kt = 0; kt < 4; kt++) {
#pragma unroll
            for (int nt = 0; nt < 8; nt++) {
                unsigned b0 = Kw[(nt * 8 + r) * KW + kt * 8 + q];
                unsigned b1 = Kw[(nt * 8 + r) * KW + kt * 8 + q + 4];
                mma_bf16(s[0][nt][0], s[0][nt][1], s[0][nt][2], s[0][nt][3],
                         aq[0][kt][0], aq[0][kt][1], aq[0][kt][2], aq[0][kt][3], b0, b1);
                mma_bf16(s[1][nt][0], s[1][nt][1], s[1][nt][2], s[1][nt][3],
                         aq[1][kt][0], aq[1][kt][1], aq[1][kt][2], aq[1][kt][3], b0, b1);
            }
        }

        // ---- online softmax (base-2), per M-frag ----
#pragma unroll
        for (int mf = 0; mf < 2; mf++) {
            float mx0 = -1e30f, mx1 = -1e30f;
#pragma unroll
            for (int nt = 0; nt < 8; nt++) {
                mx0 = fmaxf(mx0, fmaxf(s[mf][nt][0], s[mf][nt][1]));
                mx1 = fmaxf(mx1, fmaxf(s[mf][nt][2], s[mf][nt][3]));
            }
            mx0 = fmaxf(mx0, __shfl_xor_sync(0xffffffffu, mx0, 1));
            mx0 = fmaxf(mx0, __shfl_xor_sync(0xffffffffu, mx0, 2));
            mx1 = fmaxf(mx1, __shfl_xor_sync(0xffffffffu, mx1, 1));
            mx1 = fmaxf(mx1, __shfl_xor_sync(0xffffffffu, mx1, 2));

            float mn0 = fmaxf(m_i[mf][0], mx0), mn1 = fmaxf(m_i[mf][1], mx1);
            float al0 = exp2f(m_i[mf][0] - mn0), al1 = exp2f(m_i[mf][1] - mn1);
            float sum0 = 0.f, sum1 = 0.f;
#pragma unroll
            for (int nt = 0; nt < 8; nt++) {
                s[mf][nt][0] = exp2f(s[mf][nt][0] - mn0);
                s[mf][nt][1] = exp2f(s[mf][nt][1] - mn0);
                s[mf][nt][2] = exp2f(s[mf][nt][2] - mn1);
                s[mf][nt][3] = exp2f(s[mf][nt][3] - mn1);
                sum0 += s[mf][nt][0] + s[mf][nt][1];
                sum1 += s[mf][nt][2] + s[mf][nt][3];
            }
            sum0 += __shfl_xor_sync(0xffffffffu, sum0, 1);
            sum0 += __shfl_xor_sync(0xffffffffu, sum0, 2);
            sum1 += __shfl_xor_sync(0xffffffffu, sum1, 1);
            sum1 += __shfl_xor_sync(0xffffffffu, sum1, 2);

            l_i[mf][0] = l_i[mf][0] * al0 + sum0;  m_i[mf][0] = mn0;
            l_i[mf][1] = l_i[mf][1] * al1 + sum1;  m_i[mf][1] = mn1;
#pragma unroll
            for (int ct = 0; ct < 8; ct++) {
                o[mf][ct][0] *= al0; o[mf][ct][1] *= al0;
                o[mf][ct][2] *= al1; o[mf][ct][3] *= al1;
            }
        }

        // ---- O += P * V : shared V B-frags feed both M-frags ----
#pragma unroll
        for (int kt = 0; kt < 4; kt++) {
            unsigned pa[2][4];
#pragma unroll
            for (int mf = 0; mf < 2; mf++) {
                pa[mf][0] = packbf(s[mf][2*kt][0],     s[mf][2*kt][1]);
                pa[mf][1] = packbf(s[mf][2*kt][2],     s[mf][2*kt][3]);
                pa[mf][2] = packbf(s[mf][2*kt + 1][0], s[mf][2*kt + 1][1]);
                pa[mf][3] = packbf(s[mf][2*kt + 1][2], s[mf][2*kt + 1][3]);
            }
#pragma unroll
            for (int ct = 0; ct < 8; ct++) {
                unsigned b0 = Vw[(ct * 8 + r) * KW + kt * 8 + q];
                unsigned b1 = Vw[(ct * 8 + r) * KW + kt * 8 + q + 4];
                mma_bf16(o[0][ct][0], o[0][ct][1], o[0][ct][2], o[0][ct][3],
                         pa[0][0], pa[0][1], pa[0][2], pa[0][3], b0, b1);
                mma_bf16(o[1][ct][0], o[1][ct][1], o[1][ct][2], o[1][ct][3],
                         pa[1][0], pa[1][1], pa[1][2], pa[1][3], b0, b1);
            }
        }
        __syncthreads();

        // ---- prefetch tile it+2 into this (now dead) buffer ----
        int jn = (it + 2) * 64;
        if (jn < NTOK) {
            unsigned kd = sbase + buf * BUFB + doff;
            const __nv_bfloat16* ksrc = Kg + (size_t)(jn + srow) * CDIM + sh * 32;
            const __nv_bfloat16* vsrc = Vg + (size_t)srow * NTOK + jn + sh * 32;
#pragma unroll
            for (int j = 0; j < 4; j++) {
                cpa16(kd + j * 16, ksrc + j * 8);
                cpa16(kd + 9216 + j * 16, vsrc + j * 8);
            }
        }
        CP_COMMIT();
    }

    CP_WAIT0();
    __syncthreads();

    // ---- epilogue: normalize, two-phase smem transpose, write [B][C][N] ----
#pragma unroll
    for (int ph = 0; ph < 2; ph++) {
        if ((warp >> 1) == ph) {
#pragma unroll
            for (int mf = 0; mf < 2; mf++) {
                int rowL = (warp & 1) * 32 + mf * 16 + r;
                float il0 = 1.0f / l_i[mf][0], il1 = 1.0f / l_i[mf][1];
#pragma unroll
                for (int ct = 0; ct < 8; ct++) {
                    int cc = ct * 8 + 2 * q;
                    Es[rowL * 71 + cc]           = o[mf][ct][0] * il0;
                    Es[rowL * 71 + cc + 1]       = o[mf][ct][1] * il0;
                    Es[(rowL + 8) * 71 + cc]     = o[mf][ct][2] * il1;
                    Es[(rowL + 8) * 71 + cc + 1] = o[mf][ct][3] * il1;
                }
            }
        }
        __syncthreads();
        for (int e = tid; e < 4096; e += 128) {
            int c = e >> 6, n = e & 63;
            g_o[((size_t)b * CDIM + h * HD + c) * NTOK + n0 + ph * 64 + n] = Es[n * 71 + c];
        }
        __syncthreads();
    }
}

// ---------------- launch ----------------------------------------------------
extern "C" void kernel_launch(void* const* d_in, const int* in_sizes, int n_in,
                              void* d_out, int out_size)
{
    const float* x     = (const float*)d_in[0];
    const float* gamma = (const float*)d_in[1];
    const float* beta  = (const float*)d_in[2];
    const float* Wq    = (const float*)d_in[3];
    const float* bq    = (const float*)d_in[4];
    const float* Wk    = (const float*)d_in[5];
    const float* bk    = (const float*)d_in[6];
    const float* Wv    = (const float*)d_in[7];
    const float* bv    = (const float*)d_in[8];
    const float* Wo    = (const float*)d_in[9];
    const float* bo    = (const float*)d_in[10];
    float* out = (float*)d_out;

    const float SCL = 0.125f * 1.4426950408889634f;   // (1/sqrt(hd)) * log2(e)

    k_wconv<<<dim3(512, 3), 256>>>(Wq, Wk, Wv);
    k_transpose<<<dim3(CDIM/32, CDIM/32), dim3(32, 8)>>>(Wo);
    k_groupnorm<<<BATCH * GROUPS, 256>>>(x, gamma, beta);

    dim3 gg(NTOK / 128, CDIM / 64, BATCH);
    k_gemm_qkv<<<gg, 256>>>(0, bq, 0, SCL);    // Q -> g_qb (pre-scaled)
    k_gemm_qkv<<<gg, 256>>>(1, bk, 1, 1.0f);   // K -> g_kb
    k_gemm_qkv<<<gg, 256>>>(2, bv, 2, 1.0f);   // V -> g_vb (transposed)

    k_attn<<<dim3(NTOK / 128, HEADS, BATCH), 128>>>();

    k_gemm_out<<<gg, 256>>>(bo, x, out);       // out = x + g_o @ Wo^T + bo
}